// round 1
// baseline (speedup 1.0000x reference)
#include <cuda_runtime.h>
#include <math.h>

#define BB   8
#define CC   256
#define NN   4096
#define QKD  32
#define SCALE 0.17677669529663687f  /* 32^-0.5 */

// ---------------- scratch (device globals; no allocation allowed) ----------
__device__ float g_q[BB*NN*QKD];     // [b][n][32]  (scaled, +bq)
__device__ float g_k[BB*NN*QKD];     // [b][n][32]  (+bk)
__device__ float g_vt[BB*NN*CC];     // [b][n][c]   (+bv)
__device__ float g_M[BB*NN];
__device__ float g_invS[BB*NN];
__device__ float g_pM[4*BB*NN];
__device__ float g_pS[4*BB*NN];
__device__ float g_att[BB*NN*CC];    // attention out, [b][m][c]
__device__ float g_mlp[BB*NN*CC];    // mlp out, [b][m][c]
__device__ float g_W1t[CC*CC];       // [k][o]
__device__ float g_W2t[CC*CC];
__device__ float g_red[BB*64*2];
__device__ float g_mv[BB*2];

// ---------------- transpose W1/W2 to [k][o] --------------------------------
__global__ void wtrans_kernel(const float* __restrict__ W1,
                              const float* __restrict__ W2) {
    __shared__ float s[32][33];
    const float* W  = blockIdx.z ? W2 : W1;
    float*       Wt = blockIdx.z ? g_W2t : g_W1t;
    int o0 = blockIdx.x * 32, k0 = blockIdx.y * 32;
    int tx = threadIdx.x, ty = threadIdx.y;
#pragma unroll
    for (int r = 0; r < 4; r++)
        s[ty + 8*r][tx] = W[(o0 + ty + 8*r)*CC + k0 + tx];
    __syncthreads();
#pragma unroll
    for (int r = 0; r < 4; r++)
        Wt[(k0 + ty + 8*r)*CC + o0 + tx] = s[tx][ty + 8*r];
}

// ---------------- fused q/k/v projection -----------------------------------
// Treat [Wq;Wk;Wv] as one 320x256 matrix; GEMM vs x[b][c][n].
__global__ void qkv_kernel(const float* __restrict__ x,
                           const float* __restrict__ Wq, const float* __restrict__ bq,
                           const float* __restrict__ Wk, const float* __restrict__ bk,
                           const float* __restrict__ Wv, const float* __restrict__ bv) {
    __shared__ float As[32][64];    // [k][o]
    __shared__ float Bs[32][128];   // [k][n]
    int b  = blockIdx.z;
    int o0 = blockIdx.y * 64;
    int n0 = blockIdx.x * 128;
    int tid = threadIdx.x;
    int tx = tid & 15, ty = tid >> 4;
    const float* xb = x + (size_t)b * CC * NN;

    float acc[4][8];
#pragma unroll
    for (int i = 0; i < 4; i++)
#pragma unroll
        for (int j = 0; j < 8; j++) acc[i][j] = 0.f;

    for (int k0 = 0; k0 < CC; k0 += 32) {
        __syncthreads();
#pragma unroll
        for (int r = 0; r < 8; r++) {           // 2048 A elems
            int e = r*256 + tid;
            int oo = e >> 5, kk = e & 31;
            int o = o0 + oo;
            const float* Wr = (o < 32) ? (Wq + o*CC)
                            : (o < 64) ? (Wk + (o-32)*CC)
                                       : (Wv + (o-64)*CC);
            As[kk][oo] = Wr[k0 + kk];
        }
#pragma unroll
        for (int r = 0; r < 16; r++) {          // 4096 B elems
            int e = r*256 + tid;
            int kk = e >> 7, nn = e & 127;
            Bs[kk][nn] = xb[(k0 + kk)*NN + n0 + nn];
        }
        __syncthreads();
#pragma unroll
        for (int kk = 0; kk < 32; kk++) {
            float a[4], bv_[8];
#pragma unroll
            for (int i = 0; i < 4; i++) a[i] = As[kk][ty*4 + i];
#pragma unroll
            for (int j = 0; j < 8; j++) bv_[j] = Bs[kk][tx + 16*j];
#pragma unroll
            for (int i = 0; i < 4; i++)
#pragma unroll
                for (int j = 0; j < 8; j++)
                    acc[i][j] = fmaf(a[i], bv_[j], acc[i][j]);
        }
    }
#pragma unroll
    for (int i = 0; i < 4; i++) {
        int o = o0 + ty*4 + i;
#pragma unroll
        for (int j = 0; j < 8; j++) {
            int n = n0 + tx + 16*j;
            float v = acc[i][j];
            if (o < 32)       g_q[(b*NN + n)*QKD + o]        = (v + bq[o]) * SCALE;
            else if (o < 64)  g_k[(b*NN + n)*QKD + (o - 32)] = v + bk[o - 32];
            else              g_vt[(size_t)(b*NN + n)*CC + (o - 64)] = v + bv[o - 64];
        }
    }
}

// ---------------- pass 1: column-softmax stats (over m) --------------------
__global__ void stats_kernel() {
    __shared__ float qs[64*32];
    int b = blockIdx.z, ms = blockIdx.y;
    int n = blockIdx.x * 256 + threadIdx.x;
    float kr[32];
    const float* kp = g_k + (b*NN + n)*QKD;
#pragma unroll
    for (int j = 0; j < 32; j++) kr[j] = kp[j];

    float M = -1e30f, S = 0.f;
    int mbase = ms * 1024;
    for (int mc = 0; mc < 1024; mc += 64) {
        __syncthreads();
        const float* qsrc = g_q + (b*NN + mbase + mc)*QKD;
#pragma unroll
        for (int r = 0; r < 8; r++) qs[r*256 + threadIdx.x] = qsrc[r*256 + threadIdx.x];
        __syncthreads();
#pragma unroll 4
        for (int mm = 0; mm < 64; mm++) {
            const float* qr = qs + mm*32;
            float d = 0.f;
#pragma unroll
            for (int j = 0; j < 32; j++) d = fmaf(qr[j], kr[j], d);
            if (d <= M) { S += __expf(d - M); }
            else        { S = S * __expf(M - d) + 1.f; M = d; }
        }
    }
    g_pM[(ms*BB + b)*NN + n] = M;
    g_pS[(ms*BB + b)*NN + n] = S;
}

__global__ void combine_kernel() {
    int idx = blockIdx.x * 256 + threadIdx.x;   // over BB*NN
    int b = idx / NN, n = idx % NN;
    float M = -1e30f;
#pragma unroll
    for (int s = 0; s < 4; s++) M = fmaxf(M, g_pM[(s*BB + b)*NN + n]);
    float S = 0.f;
#pragma unroll
    for (int s = 0; s < 4; s++)
        S += g_pS[(s*BB + b)*NN + n] * __expf(g_pM[(s*BB + b)*NN + n] - M);
    g_M[idx] = M;
    g_invS[idx] = 1.f / S;
}

// ---------------- pass 2: out[b][m][c] = sum_n E(m,n)*vt'(n,c) -------------
#define QSTR 33
__global__ void attnout_kernel() {
    extern __shared__ float sm[];
    float* qs  = sm;               // 64 x 33 (padded)
    float* ks  = qs + 64*QSTR;     // 32 x 32
    float* Es  = ks + 32*32;       // [n][m] 32 x 64
    float* vs  = Es + 32*64;       // [n][c] 32 x 256  (pre-scaled by invS)
    float* Mch = vs + 32*256;      // 32

    int b  = blockIdx.y;
    int m0 = blockIdx.x * 64;
    int tid = threadIdx.x;
    int tx = tid & 15, ty = tid >> 4;

    {   // load q tile once (padded rows)
        const float* qsrc = g_q + (b*NN + m0)*QKD;
#pragma unroll
        for (int r = 0; r < 8; r++) {
            int e = r*256 + tid;
            qs[(e >> 5)*QSTR + (e & 31)] = qsrc[e];
        }
    }

    float acc[4][16];
#pragma unroll
    for (int i = 0; i < 4; i++)
#pragma unroll
        for (int j = 0; j < 16; j++) acc[i][j] = 0.f;

    for (int n0 = 0; n0 < NN; n0 += 32) {
        __syncthreads();
        {
            const float* ksrc = g_k + (b*NN + n0)*QKD;
#pragma unroll
            for (int r = 0; r < 4; r++) ks[r*256 + tid] = ksrc[r*256 + tid];
            if (tid < 32) Mch[tid] = g_M[b*NN + n0 + tid];
#pragma unroll
            for (int r = 0; r < 32; r++) {
                float is = g_invS[b*NN + n0 + r];
                vs[r*256 + tid] = g_vt[(size_t)(b*NN + n0 + r)*CC + tid] * is;
            }
        }
        __syncthreads();
        // E tile: 2048 dots
#pragma unroll
        for (int r = 0; r < 8; r++) {
            int e = r*256 + tid;
            int nn = e >> 6, mm = e & 63;
            const float* qr = qs + mm*QSTR;
            const float* krow = ks + nn*32;
            float d = 0.f;
#pragma unroll
            for (int j = 0; j < 32; j++) d = fmaf(qr[j], krow[j], d);
            Es[nn*64 + mm] = __expf(d - Mch[nn]);
        }
        __syncthreads();
        // GEMM: acc += E[m][n] * vs[n][c]
#pragma unroll
        for (int kk = 0; kk < 32; kk++) {
            float a[4];
#pragma unroll
            for (int i = 0; i < 4; i++) a[i] = Es[kk*64 + ty*4 + i];
#pragma unroll
            for (int j = 0; j < 16; j++) {
                float bw = vs[kk*256 + tx + 16*j];
#pragma unroll
                for (int i = 0; i < 4; i++) acc[i][j] = fmaf(a[i], bw, acc[i][j]);
            }
        }
    }
#pragma unroll
    for (int i = 0; i < 4; i++) {
        int m = m0 + ty*4 + i;
        float* dst = g_att + (size_t)(b*NN + m)*CC;
#pragma unroll
        for (int j = 0; j < 16; j++) dst[tx + 16*j] = acc[i][j];
    }
}

// ---------------- MLP: y = relu(X W1^T + b1) W2^T + b2 ---------------------
#define XSTR 257
__global__ void mlp_kernel(const float* __restrict__ b1,
                           const float* __restrict__ b2) {
    extern __shared__ float sm[];
    float* Xs  = sm;               // 64 x 257 (padded)
    float* Bsh = sm + 64*XSTR;     // 32 x 256
    int r0 = blockIdx.x * 64;
    int tid = threadIdx.x;
    int tx = tid & 15, ty = tid >> 4;

    {
        const float* src = g_att + (size_t)r0 * CC;
#pragma unroll
        for (int r = 0; r < 64; r++) Xs[r*XSTR + tid] = src[r*256 + tid];
    }

    float acc[4][16];
    // ---- GEMM1 ----
#pragma unroll
    for (int i = 0; i < 4; i++)
#pragma unroll
        for (int j = 0; j < 16; j++) acc[i][j] = 0.f;
    for (int k0 = 0; k0 < 256; k0 += 32) {
        __syncthreads();
#pragma unroll
        for (int r = 0; r < 32; r++) Bsh[r*256 + tid] = g_W1t[(k0 + r)*256 + tid];
        __syncthreads();
#pragma unroll
        for (int kk = 0; kk < 32; kk++) {
            float a[4];
#pragma unroll
            for (int i = 0; i < 4; i++) a[i] = Xs[(ty*4 + i)*XSTR + k0 + kk];
#pragma unroll
            for (int j = 0; j < 16; j++) {
                float bw = Bsh[kk*256 + tx + 16*j];
#pragma unroll
                for (int i = 0; i < 4; i++) acc[i][j] = fmaf(a[i], bw, acc[i][j]);
            }
        }
    }
    __syncthreads();
    // relu + bias -> Xs
#pragma unroll
    for (int i = 0; i < 4; i++)
#pragma unroll
        for (int j = 0; j < 16; j++) {
            int o = tx + 16*j;
            Xs[(ty*4 + i)*XSTR + o] = fmaxf(acc[i][j] + b1[o], 0.f);
        }
    __syncthreads();
    // ---- GEMM2 ----
#pragma unroll
    for (int i = 0; i < 4; i++)
#pragma unroll
        for (int j = 0; j < 16; j++) acc[i][j] = 0.f;
    for (int k0 = 0; k0 < 256; k0 += 32) {
        __syncthreads();
#pragma unroll
        for (int r = 0; r < 32; r++) Bsh[r*256 + tid] = g_W2t[(k0 + r)*256 + tid];
        __syncthreads();
#pragma unroll
        for (int kk = 0; kk < 32; kk++) {
            float a[4];
#pragma unroll
            for (int i = 0; i < 4; i++) a[i] = Xs[(ty*4 + i)*XSTR + k0 + kk];
#pragma unroll
            for (int j = 0; j < 16; j++) {
                float bw = Bsh[kk*256 + tx + 16*j];
#pragma unroll
                for (int i = 0; i < 4; i++) acc[i][j] = fmaf(a[i], bw, acc[i][j]);
            }
        }
    }
#pragma unroll
    for (int i = 0; i < 4; i++) {
        float* dst = g_mlp + (size_t)(r0 + ty*4 + i) * CC;
#pragma unroll
        for (int j = 0; j < 16; j++) {
            int o = tx + 16*j;
            dst[o] = acc[i][j] + b2[o];
        }
    }
}

// ---------------- LayerNorm ------------------------------------------------
__global__ void ln_partial() {
    __shared__ float ss[256], sq[256];
    int b = blockIdx.y, ch = blockIdx.x;
    const float* p = g_mlp + (size_t)b*NN*CC + ch*16384;
    float s = 0.f, q = 0.f;
#pragma unroll 8
    for (int r = 0; r < 64; r++) {
        float v = p[r*256 + threadIdx.x];
        s += v; q += v*v;
    }
    ss[threadIdx.x] = s; sq[threadIdx.x] = q;
    __syncthreads();
    for (int st = 128; st > 0; st >>= 1) {
        if (threadIdx.x < st) {
            ss[threadIdx.x] += ss[threadIdx.x + st];
            sq[threadIdx.x] += sq[threadIdx.x + st];
        }
        __syncthreads();
    }
    if (threadIdx.x == 0) {
        g_red[(b*64 + ch)*2 + 0] = ss[0];
        g_red[(b*64 + ch)*2 + 1] = sq[0];
    }
}

__global__ void ln_final() {
    __shared__ float ss[64], sq[64];
    int b = blockIdx.x, t = threadIdx.x;
    ss[t] = g_red[(b*64 + t)*2 + 0];
    sq[t] = g_red[(b*64 + t)*2 + 1];
    __syncthreads();
    for (int st = 32; st > 0; st >>= 1) {
        if (t < st) { ss[t] += ss[t + st]; sq[t] += sq[t + st]; }
        __syncthreads();
    }
    if (t == 0) {
        const float inv = 1.0f / (float)(NN * CC);
        float mean = ss[0] * inv;
        float var  = sq[0] * inv - mean*mean;
        g_mv[b*2 + 0] = mean;
        g_mv[b*2 + 1] = rsqrtf(var + 1e-5f);
    }
}

__global__ void ln_apply(const float* __restrict__ gamma,
                         const float* __restrict__ beta,
                         float* __restrict__ out) {
    __shared__ float s[32][33];
    int b = blockIdx.z, c0 = blockIdx.y*32, n0 = blockIdx.x*32;
    int tx = threadIdx.x, ty = threadIdx.y;
    float mean = g_mv[b*2], rstd = g_mv[b*2 + 1];
#pragma unroll
    for (int r = 0; r < 4; r++) {
        int n = n0 + ty + 8*r;
        s[ty + 8*r][tx] = g_mlp[(size_t)(b*NN + n)*CC + c0 + tx];
    }
    __syncthreads();
#pragma unroll
    for (int r = 0; r < 4; r++) {
        int c = c0 + ty + 8*r;
        int n = n0 + tx;
        float v = s[tx][ty + 8*r];
        size_t gi = (size_t)c*NN + n;
        out[(size_t)b*CC*NN + gi] = (v - mean)*rstd*gamma[gi] + beta[gi];
    }
}

// ---------------- launch ----------------------------------------------------
extern "C" void kernel_launch(void* const* d_in, const int* in_sizes, int n_in,
                              void* d_out, int out_size) {
    const float* x     = (const float*)d_in[0];
    const float* Wq    = (const float*)d_in[1];
    const float* bq    = (const float*)d_in[2];
    const float* Wk    = (const float*)d_in[3];
    const float* bk    = (const float*)d_in[4];
    const float* Wv    = (const float*)d_in[5];
    const float* bv    = (const float*)d_in[6];
    const float* W1    = (const float*)d_in[7];
    const float* b1    = (const float*)d_in[8];
    const float* W2    = (const float*)d_in[9];
    const float* b2    = (const float*)d_in[10];
    const float* gamma = (const float*)d_in[11];
    const float* beta  = (const float*)d_in[12];
    float* out = (float*)d_out;

    const int attn_smem = (64*QSTR + 32*32 + 32*64 + 32*256 + 32) * 4;
    const int mlp_smem  = (64*XSTR + 32*256) * 4;
    cudaFuncSetAttribute(attnout_kernel, cudaFuncAttributeMaxDynamicSharedMemorySize, attn_smem);
    cudaFuncSetAttribute(mlp_kernel,     cudaFuncAttributeMaxDynamicSharedMemorySize, mlp_smem);

    wtrans_kernel<<<dim3(8, 8, 2), dim3(32, 8)>>>(W1, W2);
    qkv_kernel<<<dim3(NN/128, 5, BB), 256>>>(x, Wq, bq, Wk, bk, Wv, bv);
    stats_kernel<<<dim3(16, 4, BB), 256>>>();
    combine_kernel<<<(BB*NN)/256, 256>>>();
    attnout_kernel<<<dim3(NN/64, BB), 256, attn_smem>>>();
    mlp_kernel<<<(BB*NN)/64, 256, mlp_smem>>>(b1, b2);
    ln_partial<<<dim3(64, BB), 256>>>();
    ln_final<<<BB, 64>>>();
    ln_apply<<<dim3(NN/32, CC/32, BB), dim3(32, 8)>>>(gamma, beta, out);
}

// round 3
// speedup vs baseline: 2.0971x; 2.0971x over previous
#include <cuda_runtime.h>
#include <math.h>

#define BB   8
#define CC   256
#define NN   4096
#define QKD  32
#define SCALE 0.17677669529663687f  /* 32^-0.5 */
#define VSTR 264

// ---------------- scratch ---------------------------------------------------
__device__ float g_q[BB*NN*QKD];      // [b][n][32]  (scaled, +bq)
__device__ float g_k[BB*NN*QKD];      // [b][n][32]  (+bk)
__device__ float g_vt[BB*NN*CC];      // [b][n][c]   (+bv)
__device__ float g_M[BB*NN];          // softmax shift (upper bound M')
__device__ float g_invS[BB*NN];
__device__ float g_att[BB*NN*CC];     // attention out, [b][m][c]
__device__ float g_mlp[BB*NN*CC];     // mlp out, [b][m][c]
__device__ float g_W1t[CC*CC];        // [k][o]
__device__ float g_W2t[CC*CC];
__device__ float g_qn2[BB*NN];
__device__ float g_kn2[BB*NN];
__device__ float g_qmax[BB];
__device__ float g_red[BB*64*2];
__device__ float g_mv[BB*2];

// ---------------- tf32 helpers ----------------------------------------------
__device__ __forceinline__ float tf32r(float x) {
    unsigned u;
    asm("cvt.rna.tf32.f32 %0, %1;" : "=r"(u) : "f"(x));
    return __uint_as_float(u);
}
__device__ __forceinline__ void mma8(float* c,
                                     unsigned a0, unsigned a1, unsigned a2, unsigned a3,
                                     unsigned b0, unsigned b1) {
    asm volatile("mma.sync.aligned.m16n8k8.row.col.f32.tf32.tf32.f32 "
                 "{%0,%1,%2,%3}, {%4,%5,%6,%7}, {%8,%9}, {%0,%1,%2,%3};\n"
                 : "+f"(c[0]), "+f"(c[1]), "+f"(c[2]), "+f"(c[3])
                 : "r"(a0), "r"(a1), "r"(a2), "r"(a3), "r"(b0), "r"(b1));
}
#define FU __float_as_uint

// ---------------- transpose W1/W2 to [k][o] --------------------------------
__global__ void wtrans_kernel(const float* __restrict__ W1,
                              const float* __restrict__ W2) {
    __shared__ float s[32][33];
    const float* W  = blockIdx.z ? W2 : W1;
    float*       Wt = blockIdx.z ? g_W2t : g_W1t;
    int o0 = blockIdx.x * 32, k0 = blockIdx.y * 32;
    int tx = threadIdx.x, ty = threadIdx.y;
#pragma unroll
    for (int r = 0; r < 4; r++)
        s[ty + 8*r][tx] = W[(o0 + ty + 8*r)*CC + k0 + tx];
    __syncthreads();
#pragma unroll
    for (int r = 0; r < 4; r++)
        Wt[(k0 + ty + 8*r)*CC + o0 + tx] = s[tx][ty + 8*r];
}

// ---------------- fused q/k/v projection (scalar) ---------------------------
__global__ void qkv_kernel(const float* __restrict__ x,
                           const float* __restrict__ Wq, const float* __restrict__ bq,
                           const float* __restrict__ Wk, const float* __restrict__ bk,
                           const float* __restrict__ Wv, const float* __restrict__ bv) {
    __shared__ float As[32][64];
    __shared__ float Bs[32][128];
    int b  = blockIdx.z;
    int o0 = blockIdx.y * 64;
    int n0 = blockIdx.x * 128;
    int tid = threadIdx.x;
    int tx = tid & 15, ty = tid >> 4;
    const float* xb = x + (size_t)b * CC * NN;

    float acc[4][8];
#pragma unroll
    for (int i = 0; i < 4; i++)
#pragma unroll
        for (int j = 0; j < 8; j++) acc[i][j] = 0.f;

    for (int k0 = 0; k0 < CC; k0 += 32) {
        __syncthreads();
#pragma unroll
        for (int r = 0; r < 8; r++) {
            int e = r*256 + tid;
            int oo = e >> 5, kk = e & 31;
            int o = o0 + oo;
            const float* Wr = (o < 32) ? (Wq + o*CC)
                            : (o < 64) ? (Wk + (o-32)*CC)
                                       : (Wv + (o-64)*CC);
            As[kk][oo] = Wr[k0 + kk];
        }
#pragma unroll
        for (int r = 0; r < 16; r++) {
            int e = r*256 + tid;
            int kk = e >> 7, nn = e & 127;
            Bs[kk][nn] = xb[(k0 + kk)*NN + n0 + nn];
        }
        __syncthreads();
#pragma unroll
        for (int kk = 0; kk < 32; kk++) {
            float a[4], bw[8];
#pragma unroll
            for (int i = 0; i < 4; i++) a[i] = As[kk][ty*4 + i];
#pragma unroll
            for (int j = 0; j < 8; j++) bw[j] = Bs[kk][tx + 16*j];
#pragma unroll
            for (int i = 0; i < 4; i++)
#pragma unroll
                for (int j = 0; j < 8; j++)
                    acc[i][j] = fmaf(a[i], bw[j], acc[i][j]);
        }
    }
#pragma unroll
    for (int i = 0; i < 4; i++) {
        int o = o0 + ty*4 + i;
#pragma unroll
        for (int j = 0; j < 8; j++) {
            int n = n0 + tx + 16*j;
            float v = acc[i][j];
            if (o < 32)       g_q[(b*NN + n)*QKD + o]        = (v + bq[o]) * SCALE;
            else if (o < 64)  g_k[(b*NN + n)*QKD + (o - 32)] = v + bk[o - 32];
            else              g_vt[(size_t)(b*NN + n)*CC + (o - 64)] = v + bv[o - 64];
        }
    }
}

// ---------------- softmax shift: M'[b][n] = ||k_n|| * max_m ||q_m|| ---------
__global__ void bound_norms() {
    int idx = blockIdx.x*256 + threadIdx.x;
    const float* qp = g_q + idx*QKD;
    const float* kp = g_k + idx*QKD;
    float qs = 0.f, ks = 0.f;
#pragma unroll
    for (int j = 0; j < QKD; j++) { qs = fmaf(qp[j], qp[j], qs); ks = fmaf(kp[j], kp[j], ks); }
    g_qn2[idx] = qs; g_kn2[idx] = ks;
}
__global__ void bound_qmax() {
    __shared__ float s[256];
    int b = blockIdx.x;
    float m = 0.f;
    for (int i = threadIdx.x; i < NN; i += 256) m = fmaxf(m, g_qn2[b*NN + i]);
    s[threadIdx.x] = m; __syncthreads();
    for (int st = 128; st > 0; st >>= 1) {
        if (threadIdx.x < st) s[threadIdx.x] = fmaxf(s[threadIdx.x], s[threadIdx.x + st]);
        __syncthreads();
    }
    if (threadIdx.x == 0) g_qmax[b] = s[0];
}
__global__ void bound_M() {
    int idx = blockIdx.x*256 + threadIdx.x;
    int b = idx >> 12;
    g_M[idx] = sqrtf(g_kn2[idx] * g_qmax[b]);
}

// ---------------- stats: S[n] = sum_m exp(q_m.k_n - M'[n]) via mma ----------
__global__ void stats_kernel2() {
    __shared__ float ks[128*40];
    __shared__ float qs[64*40];
    __shared__ float Mch[128];
    int b = blockIdx.y, n0 = blockIdx.x*128;
    int tid = threadIdx.x, w = tid >> 5, lane = tid & 31, g = lane >> 2, tig = lane & 3;

#pragma unroll
    for (int r = 0; r < 16; r++) {
        int e = r*256 + tid; int row = e >> 5, col = e & 31;
        ks[row*40 + col] = tf32r(g_k[(b*NN + n0 + row)*QKD + col]);
    }
    if (tid < 128) Mch[tid] = g_M[b*NN + n0 + tid];
    __syncthreads();

    // hoisted B fragments (this warp's 16 n-cols, fixed all kernel)
    unsigned bb[2][4][2];
#pragma unroll
    for (int t = 0; t < 2; t++) {
        int nb = w*16 + t*8;
#pragma unroll
        for (int k4 = 0; k4 < 4; k4++) {
            int k0 = k4*8;
            bb[t][k4][0] = FU(ks[(nb + g)*40 + k0 + tig]);
            bb[t][k4][1] = FU(ks[(nb + g)*40 + k0 + tig + 4]);
        }
    }

    float scol[4] = {0.f, 0.f, 0.f, 0.f};
    for (int m0 = 0; m0 < NN; m0 += 64) {
        __syncthreads();
#pragma unroll
        for (int r = 0; r < 8; r++) {
            int e = r*256 + tid; int row = e >> 5, col = e & 31;
            qs[row*40 + col] = tf32r(g_q[(b*NN + m0 + row)*QKD + col]);
        }
        __syncthreads();
#pragma unroll
        for (int sw = 0; sw < 4; sw++) {
            unsigned a[4][4];
#pragma unroll
            for (int k4 = 0; k4 < 4; k4++) {
                int k0 = k4*8;
                a[k4][0] = FU(qs[(sw*16 + g)*40     + k0 + tig]);
                a[k4][1] = FU(qs[(sw*16 + 8 + g)*40 + k0 + tig]);
                a[k4][2] = FU(qs[(sw*16 + g)*40     + k0 + tig + 4]);
                a[k4][3] = FU(qs[(sw*16 + 8 + g)*40 + k0 + tig + 4]);
            }
#pragma unroll
            for (int t = 0; t < 2; t++) {
                float d[4] = {0.f, 0.f, 0.f, 0.f};
#pragma unroll
                for (int k4 = 0; k4 < 4; k4++)
                    mma8(d, a[k4][0], a[k4][1], a[k4][2], a[k4][3], bb[t][k4][0], bb[t][k4][1]);
                int nb = w*16 + t*8;
                float M0 = Mch[nb + 2*tig], M1 = Mch[nb + 2*tig + 1];
                scol[t*2]     += __expf(d[0] - M0) + __expf(d[2] - M0);
                scol[t*2 + 1] += __expf(d[1] - M1) + __expf(d[3] - M1);
            }
        }
    }
#pragma unroll
    for (int off = 16; off >= 4; off >>= 1)
#pragma unroll
        for (int i = 0; i < 4; i++)
            scol[i] += __shfl_down_sync(0xffffffffu, scol[i], off);
    if (lane < 4) {
#pragma unroll
        for (int t = 0; t < 2; t++)
#pragma unroll
            for (int p = 0; p < 2; p++) {
                int n = w*16 + t*8 + 2*lane + p;
                g_invS[b*NN + n0 + n] = 1.f / scol[t*2 + p];
            }
    }
}

// ---------------- attnout: logits(mma)+exp -> PV GEMM (mma) -----------------
__global__ void __launch_bounds__(256, 2) attnout_kernel2() {
    extern __shared__ float sm[];
    float* qs  = sm;                 // 64*40
    float* ksm = qs  + 64*40;        // 32*40
    float* Es  = ksm + 32*40;        // 64*40
    float* vs  = Es  + 64*40;        // 32*VSTR (pre-scaled by invS)
    float* Mch = vs  + 32*VSTR;      // 32

    int b = blockIdx.y, m0 = blockIdx.x*64;
    int tid = threadIdx.x, w = tid >> 5, lane = tid & 31, g = lane >> 2, tig = lane & 3;
    int mw = w & 3, cw = w >> 2;     // PV roles
    int sw = w & 3, np = w >> 2;     // logits roles

#pragma unroll
    for (int r = 0; r < 8; r++) {
        int e = r*256 + tid; int row = e >> 5, col = e & 31;
        qs[row*40 + col] = tf32r(g_q[(b*NN + m0 + row)*QKD + col]);
    }

    float acc[16][4];
#pragma unroll
    for (int i = 0; i < 16; i++)
#pragma unroll
        for (int j = 0; j < 4; j++) acc[i][j] = 0.f;

    for (int n0 = 0; n0 < NN; n0 += 32) {
        __syncthreads();
#pragma unroll
        for (int r = 0; r < 4; r++) {
            int e = r*256 + tid; int row = e >> 5, col = e & 31;
            ksm[row*40 + col] = tf32r(g_k[(b*NN + n0 + row)*QKD + col]);
        }
        if (tid < 32) Mch[tid] = g_M[b*NN + n0 + tid];
#pragma unroll 8
        for (int r = 0; r < 32; r++) {
            float is = g_invS[b*NN + n0 + r];
            vs[r*VSTR + tid] = tf32r(g_vt[(size_t)(b*NN + n0 + r)*CC + tid] * is);
        }
        __syncthreads();
        // ---- logits + exp -> Es
        {
            unsigned a[4][4];
#pragma unroll
            for (int k4 = 0; k4 < 4; k4++) {
                int k0 = k4*8;
                a[k4][0] = FU(qs[(sw*16 + g)*40     + k0 + tig]);
                a[k4][1] = FU(qs[(sw*16 + 8 + g)*40 + k0 + tig]);
                a[k4][2] = FU(qs[(sw*16 + g)*40     + k0 + tig + 4]);
                a[k4][3] = FU(qs[(sw*16 + 8 + g)*40 + k0 + tig + 4]);
            }
#pragma unroll
            for (int t = 0; t < 2; t++) {
                int nb = np*16 + t*8;
                float d[4] = {0.f, 0.f, 0.f, 0.f};
#pragma unroll
                for (int k4 = 0; k4 < 4; k4++) {
                    int k0 = k4*8;
                    unsigned b0 = FU(ksm[(nb + g)*40 + k0 + tig]);
                    unsigned b1 = FU(ksm[(nb + g)*40 + k0 + tig + 4]);
                    mma8(d, a[k4][0], a[k4][1], a[k4][2], a[k4][3], b0, b1);
                }
                float M0 = Mch[nb + 2*tig], M1 = Mch[nb + 2*tig + 1];
                Es[(sw*16 + g)*40     + nb + 2*tig]     = tf32r(__expf(d[0] - M0));
                Es[(sw*16 + g)*40     + nb + 2*tig + 1] = tf32r(__expf(d[1] - M1));
                Es[(sw*16 + 8 + g)*40 + nb + 2*tig]     = tf32r(__expf(d[2] - M0));
                Es[(sw*16 + 8 + g)*40 + nb + 2*tig + 1] = tf32r(__expf(d[3] - M1));
            }
        }
        __syncthreads();
        // ---- PV: acc += E[m][n] * vs[n][c]
#pragma unroll
        for (int k4 = 0; k4 < 4; k4++) {
            int k0 = k4*8;
            unsigned a0 = FU(Es[(mw*16 + g)*40     + k0 + tig]);
            unsigned a1 = FU(Es[(mw*16 + 8 + g)*40 + k0 + tig]);
            unsigned a2 = FU(Es[(mw*16 + g)*40     + k0 + tig + 4]);
            unsigned a3 = FU(Es[(mw*16 + 8 + g)*40 + k0 + tig + 4]);
#pragma unroll
            for (int t8 = 0; t8 < 16; t8++) {
                int col = cw*128 + t8*8;
                unsigned b0 = FU(vs[(k0 + tig)*VSTR     + col + g]);
                unsigned b1 = FU(vs[(k0 + tig + 4)*VSTR + col + g]);
                mma8(acc[t8], a0, a1, a2, a3, b0, b1);
            }
        }
    }
    // epilogue
    {
        int row = b*NN + m0 + mw*16 + g;
        float2* d0 = (float2*)(g_att + (size_t)row*CC);
        float2* d1 = (float2*)(g_att + (size_t)(row + 8)*CC);
#pragma unroll
        for (int t8 = 0; t8 < 16; t8++) {
            int cix = (cw*128 + t8*8 + 2*tig) >> 1;
            d0[cix] = make_float2(acc[t8][0], acc[t8][1]);
            d1[cix] = make_float2(acc[t8][2], acc[t8][3]);
        }
    }
}

// ---------------- MLP via mma: relu(X W1^T + b1) W2^T + b2 ------------------
__global__ void __launch_bounds__(256, 2) mlp_kernel2(const float* __restrict__ b1,
                                                      const float* __restrict__ b2) {
    extern __shared__ float sm[];
    float* Xs  = sm;              // 64*40
    float* W1s = Xs  + 64*40;     // 32*40
    float* Hs  = W1s + 32*40;     // 64*40
    float* W2s = Hs  + 64*40;     // 32*VSTR

    int m0 = blockIdx.x*64;
    int tid = threadIdx.x, w = tid >> 5, lane = tid & 31, g = lane >> 2, tig = lane & 3;
    int mw = w & 3, cw = w >> 2;
    int sw = w & 3, np = w >> 2;

    float acc2[16][4];
#pragma unroll
    for (int i = 0; i < 16; i++)
#pragma unroll
        for (int j = 0; j < 4; j++) acc2[i][j] = 0.f;

    for (int slab = 0; slab < 8; slab++) {
        float acc1[2][4];
#pragma unroll
        for (int t = 0; t < 2; t++)
#pragma unroll
            for (int j = 0; j < 4; j++) acc1[t][j] = 0.f;

        for (int kc = 0; kc < 8; kc++) {
            __syncthreads();
#pragma unroll
            for (int r = 0; r < 8; r++) {
                int e = r*256 + tid; int row = e >> 5, col = e & 31;
                Xs[row*40 + col] = tf32r(g_att[(size_t)(m0 + row)*CC + kc*32 + col]);
            }
#pragma unroll
            for (int r = 0; r < 4; r++) {
                int e = r*256 + tid; int row = e >> 5, col = e & 31;
                W1s[row*40 + col] = tf32r(g_W1t[(kc*32 + row)*CC + slab*32 + col]);
            }
            __syncthreads();
            unsigned a[4][4];
#pragma unroll
            for (int k4 = 0; k4 < 4; k4++) {
                int k0 = k4*8;
                a[k4][0] = FU(Xs[(sw*16 + g)*40     + k0 + tig]);
                a[k4][1] = FU(Xs[(sw*16 + 8 + g)*40 + k0 + tig]);
                a[k4][2] = FU(Xs[(sw*16 + g)*40     + k0 + tig + 4]);
                a[k4][3] = FU(Xs[(sw*16 + 8 + g)*40 + k0 + tig + 4]);
            }
#pragma unroll
            for (int t = 0; t < 2; t++) {
                int nb = np*16 + t*8;
#pragma unroll
                for (int k4 = 0; k4 < 4; k4++) {
                    int k0 = k4*8;
                    unsigned b0 = FU(W1s[(k0 + tig)*40     + nb + g]);
                    unsigned b1 = FU(W1s[(k0 + tig + 4)*40 + nb + g]);
                    mma8(acc1[t], a[k4][0], a[k4][1], a[k4][2], a[k4][3], b0, b1);
                }
            }
        }
        // relu + bias -> Hs (tf32)
#pragma unroll
        for (int t = 0; t < 2; t++) {
            int nb = np*16 + t*8;
            float bb0 = b1[slab*32 + nb + 2*tig];
            float bb1 = b1[slab*32 + nb + 2*tig + 1];
            Hs[(sw*16 + g)*40     + nb + 2*tig]     = tf32r(fmaxf(acc1[t][0] + bb0, 0.f));
            Hs[(sw*16 + g)*40     + nb + 2*tig + 1] = tf32r(fmaxf(acc1[t][1] + bb1, 0.f));
            Hs[(sw*16 + 8 + g)*40 + nb + 2*tig]     = tf32r(fmaxf(acc1[t][2] + bb0, 0.f));
            Hs[(sw*16 + 8 + g)*40 + nb + 2*tig + 1] = tf32r(fmaxf(acc1[t][3] + bb1, 0.f));
        }
#pragma unroll 8
        for (int r = 0; r < 32; r++)
            W2s[r*VSTR + tid] = tf32r(g_W2t[(slab*32 + r)*CC + tid]);
        __syncthreads();
        // GEMM2 partial: acc2 += H_slab * W2t[slab rows]
#pragma unroll
        for (int k4 = 0; k4 < 4; k4++) {
            int k0 = k4*8;
            unsigned a0 = FU(Hs[(mw*16 + g)*40     + k0 + tig]);
            unsigned a1 = FU(Hs[(mw*16 + 8 + g)*40 + k0 + tig]);
            unsigned a2 = FU(Hs[(mw*16 + g)*40     + k0 + tig + 4]);
            unsigned a3 = FU(Hs[(mw*16 + 8 + g)*40 + k0 + tig + 4]);
#pragma unroll
            for (int t8 = 0; t8 < 16; t8++) {
                int col = cw*128 + t8*8;
                unsigned b0 = FU(W2s[(k0 + tig)*VSTR     + col + g]);
                unsigned b1 = FU(W2s[(k0 + tig + 4)*VSTR + col + g]);
                mma8(acc2[t8], a0, a1, a2, a3, b0, b1);
            }
        }
    }
    // epilogue + b2
    {
        int row = m0 + mw*16 + g;
#pragma unroll
        for (int t8 = 0; t8 < 16; t8++) {
            int col = cw*128 + t8*8 + 2*tig;
            g_mlp[(size_t)row*CC + col]           = acc2[t8][0] + b2[col];
            g_mlp[(size_t)row*CC + col + 1]       = acc2[t8][1] + b2[col + 1];
            g_mlp[(size_t)(row + 8)*CC + col]     = acc2[t8][2] + b2[col];
            g_mlp[(size_t)(row + 8)*CC + col + 1] = acc2[t8][3] + b2[col + 1];
        }
    }
}

// ---------------- LayerNorm ------------------------------------------------
__global__ void ln_partial() {
    __shared__ float ss[256], sq[256];
    int b = blockIdx.y, ch = blockIdx.x;
    const float* p = g_mlp + (size_t)b*NN*CC + ch*16384;
    float s = 0.f, q = 0.f;
#pragma unroll 8
    for (int r = 0; r < 64; r++) {
        float v = p[r*256 + threadIdx.x];
        s += v; q += v*v;
    }
    ss[threadIdx.x] = s; sq[threadIdx.x] = q;
    __syncthreads();
    for (int st = 128; st > 0; st >>= 1) {
        if (threadIdx.x < st) {
            ss[threadIdx.x] += ss[threadIdx.x + st];
            sq[threadIdx.x] += sq[threadIdx.x + st];
        }
        __syncthreads();
    }
    if (threadIdx.x == 0) {
        g_red[(b*64 + ch)*2 + 0] = ss[0];
        g_red[(b*64 + ch)*2 + 1] = sq[0];
    }
}

__global__ void ln_final() {
    __shared__ float ss[64], sq[64];
    int b = blockIdx.x, t = threadIdx.x;
    ss[t] = g_red[(b*64 + t)*2 + 0];
    sq[t] = g_red[(b*64 + t)*2 + 1];
    __syncthreads();
    for (int st = 32; st > 0; st >>= 1) {
        if (t < st) { ss[t] += ss[t + st]; sq[t] += sq[t + st]; }
        __syncthreads();
    }
    if (t == 0) {
        const float inv = 1.0f / (float)(NN * CC);
        float mean = ss[0] * inv;
        float var  = sq[0] * inv - mean*mean;
        g_mv[b*2 + 0] = mean;
        g_mv[b*2 + 1] = rsqrtf(var + 1e-5f);
    }
}

__global__ void ln_apply(const float* __restrict__ gamma,
                         const float* __restrict__ beta,
                         float* __restrict__ out) {
    __shared__ float s[32][33];
    int b = blockIdx.z, c0 = blockIdx.y*32, n0 = blockIdx.x*32;
    int tx = threadIdx.x, ty = threadIdx.y;
    float mean = g_mv[b*2], rstd = g_mv[b*2 + 1];
#pragma unroll
    for (int r = 0; r < 4; r++) {
        int n = n0 + ty + 8*r;
        s[ty + 8*r][tx] = g_mlp[(size_t)(b*NN + n)*CC + c0 + tx];
    }
    __syncthreads();
#pragma unroll
    for (int r = 0; r < 4; r++) {
        int c = c0 + ty + 8*r;
        int n = n0 + tx;
        float v = s[tx][ty + 8*r];
        size_t gi = (size_t)c*NN + n;
        out[(size_t)b*CC*NN + gi] = (v - mean)*rstd*gamma[gi] + beta[gi];
    }
}

// ---------------- launch ----------------------------------------------------
extern "C" void kernel_launch(void* const* d_in, const int* in_sizes, int n_in,
                              void* d_out, int out_size) {
    const float* x     = (const float*)d_in[0];
    const float* Wq    = (const float*)d_in[1];
    const float* bq    = (const float*)d_in[2];
    const float* Wk    = (const float*)d_in[3];
    const float* bk    = (const float*)d_in[4];
    const float* Wv    = (const float*)d_in[5];
    const float* bv    = (const float*)d_in[6];
    const float* W1    = (const float*)d_in[7];
    const float* b1    = (const float*)d_in[8];
    const float* W2    = (const float*)d_in[9];
    const float* b2    = (const float*)d_in[10];
    const float* gamma = (const float*)d_in[11];
    const float* beta  = (const float*)d_in[12];
    float* out = (float*)d_out;

    const int attn_smem = (64*40 + 32*40 + 64*40 + 32*VSTR + 32) * 4;
    const int mlp_smem  = (64*40 + 32*40 + 64*40 + 32*VSTR) * 4;
    cudaFuncSetAttribute(attnout_kernel2, cudaFuncAttributeMaxDynamicSharedMemorySize, attn_smem);
    cudaFuncSetAttribute(mlp_kernel2,     cudaFuncAttributeMaxDynamicSharedMemorySize, mlp_smem);

    wtrans_kernel<<<dim3(8, 8, 2), dim3(32, 8)>>>(W1, W2);
    qkv_kernel<<<dim3(NN/128, 5, BB), 256>>>(x, Wq, bq, Wk, bk, Wv, bv);
    bound_norms<<<(BB*NN)/256, 256>>>();
    bound_qmax<<<BB, 256>>>();
    bound_M<<<(BB*NN)/256, 256>>>();
    stats_kernel2<<<dim3(NN/128, BB), 256>>>();
    attnout_kernel2<<<dim3(NN/64, BB), 256, attn_smem>>>();
    mlp_kernel2<<<(BB*NN)/64, 256, mlp_smem>>>(b1, b2);
    ln_partial<<<dim3(64, BB), 256>>>();
    ln_final<<<BB, 64>>>();
    ln_apply<<<dim3(NN/32, CC/32, BB), dim3(32, 8)>>>(gamma, beta, out);
}

// round 4
// speedup vs baseline: 2.7907x; 1.3308x over previous
#include <cuda_runtime.h>
#include <cuda_fp16.h>
#include <math.h>

#define BB   8
#define CC   256
#define NN   4096
#define QKD  32
#define SCALE 0.17677669529663687f  /* 32^-0.5 */
#define VSTR 264

// ---------------- scratch ---------------------------------------------------
__device__ float g_q[BB*NN*QKD];      // [b][n][32]  (scaled, +bq)
__device__ float g_k[BB*NN*QKD];      // [b][n][32]  (+bk)
__device__ float g_vt[BB*NN*CC];      // [b][n][c]   (+bv; later *= invS, tf32)
__device__ float g_M[BB*NN];          // softmax shift (upper bound M')
__device__ float g_invS[BB*NN];
__device__ __half g_E[(size_t)BB*NN*NN];   // E[b][m][n] fp16, 268 MB
__device__ float g_att[BB*NN*CC];     // attention out, [b][m][c]
__device__ float g_mlp[BB*NN*CC];     // mlp out, [b][m][c]
__device__ float g_W1t[CC*CC];        // [k][o]
__device__ float g_W2t[CC*CC];
__device__ float g_qn2[BB*NN];
__device__ float g_kn2[BB*NN];
__device__ float g_qmax[BB];
__device__ float g_red[BB*64*2];
__device__ float g_mv[BB*2];

// ---------------- tf32 helpers ----------------------------------------------
__device__ __forceinline__ float tf32r(float x) {
    unsigned u;
    asm("cvt.rna.tf32.f32 %0, %1;" : "=r"(u) : "f"(x));
    return __uint_as_float(u);
}
__device__ __forceinline__ void mma8(float* c,
                                     unsigned a0, unsigned a1, unsigned a2, unsigned a3,
                                     unsigned b0, unsigned b1) {
    asm volatile("mma.sync.aligned.m16n8k8.row.col.f32.tf32.tf32.f32 "
                 "{%0,%1,%2,%3}, {%4,%5,%6,%7}, {%8,%9}, {%0,%1,%2,%3};\n"
                 : "+f"(c[0]), "+f"(c[1]), "+f"(c[2]), "+f"(c[3])
                 : "r"(a0), "r"(a1), "r"(a2), "r"(a3), "r"(b0), "r"(b1));
}
#define FU __float_as_uint

// ---------------- transpose W1/W2 to [k][o] --------------------------------
__global__ void wtrans_kernel(const float* __restrict__ W1,
                              const float* __restrict__ W2) {
    __shared__ float s[32][33];
    const float* W  = blockIdx.z ? W2 : W1;
    float*       Wt = blockIdx.z ? g_W2t : g_W1t;
    int o0 = blockIdx.x * 32, k0 = blockIdx.y * 32;
    int tx = threadIdx.x, ty = threadIdx.y;
#pragma unroll
    for (int r = 0; r < 4; r++)
        s[ty + 8*r][tx] = W[(o0 + ty + 8*r)*CC + k0 + tx];
    __syncthreads();
#pragma unroll
    for (int r = 0; r < 4; r++)
        Wt[(k0 + ty + 8*r)*CC + o0 + tx] = s[tx][ty + 8*r];
}

// ---------------- q/k/v projection via mma ----------------------------------
// out[o][n] = sum_c W[o][c] x[c][n];  A = x^T (row n, col c), B = W (col o, row c)
#define XS 72
__global__ void qkv_mma(const float* __restrict__ x,
                        const float* __restrict__ Wq, const float* __restrict__ bq,
                        const float* __restrict__ Wk, const float* __restrict__ bk,
                        const float* __restrict__ Wv, const float* __restrict__ bv) {
    __shared__ float xs[32*XS];    // [c][n], padded
    __shared__ float ws[64*40];    // [o][c], padded
    int b  = blockIdx.z;
    int o0 = blockIdx.y * 64;
    int n0 = blockIdx.x * 64;
    int tid = threadIdx.x, w = tid >> 5, lane = tid & 31, g = lane >> 2, tig = lane & 3;
    int sw = w & 3, np = w >> 2;
    const float* xb = x + (size_t)b * CC * NN;

    float acc[4][4];
#pragma unroll
    for (int i = 0; i < 4; i++)
#pragma unroll
        for (int j = 0; j < 4; j++) acc[i][j] = 0.f;

    for (int c0 = 0; c0 < CC; c0 += 32) {
        __syncthreads();
#pragma unroll
        for (int r = 0; r < 8; r++) {
            int e = r*256 + tid; int cc = e >> 6, nn = e & 63;
            xs[cc*XS + nn] = tf32r(xb[(c0 + cc)*NN + n0 + nn]);
        }
#pragma unroll
        for (int r = 0; r < 8; r++) {
            int e = r*256 + tid; int oo = e >> 5, cc = e & 31;
            int o = o0 + oo;
            const float* Wr = (o < 32) ? (Wq + o*CC)
                            : (o < 64) ? (Wk + (o-32)*CC)
                                       : (Wv + (o-64)*CC);
            ws[oo*40 + cc] = tf32r(Wr[c0 + cc]);
        }
        __syncthreads();
#pragma unroll
        for (int k4 = 0; k4 < 4; k4++) {
            int k0 = k4*8;
            unsigned a0 = FU(xs[(k0 + tig)*XS     + sw*16 + g]);
            unsigned a1 = FU(xs[(k0 + tig)*XS     + sw*16 + 8 + g]);
            unsigned a2 = FU(xs[(k0 + tig + 4)*XS + sw*16 + g]);
            unsigned a3 = FU(xs[(k0 + tig + 4)*XS + sw*16 + 8 + g]);
#pragma unroll
            for (int t8 = 0; t8 < 4; t8++) {
                int oc = np*32 + t8*8 + g;
                unsigned b0 = FU(ws[oc*40 + k0 + tig]);
                unsigned b1 = FU(ws[oc*40 + k0 + tig + 4]);
                mma8(acc[t8], a0, a1, a2, a3, b0, b1);
            }
        }
    }
#pragma unroll
    for (int t8 = 0; t8 < 4; t8++) {
#pragma unroll
        for (int rr = 0; rr < 2; rr++) {
#pragma unroll
            for (int cc = 0; cc < 2; cc++) {
                int n = n0 + sw*16 + g + rr*8;
                int o = o0 + np*32 + t8*8 + 2*tig + cc;
                float v = acc[t8][rr*2 + cc];
                if (o < 32)       g_q[(b*NN + n)*QKD + o]        = (v + __ldg(bq + o)) * SCALE;
                else if (o < 64)  g_k[(b*NN + n)*QKD + (o - 32)] = v + __ldg(bk + o - 32);
                else              g_vt[(size_t)(b*NN + n)*CC + (o - 64)] = v + __ldg(bv + o - 64);
            }
        }
    }
}

// ---------------- softmax shift: M'[b][n] = ||k_n|| * max_m ||q_m|| ---------
__global__ void bound_norms() {
    int idx = blockIdx.x*256 + threadIdx.x;
    const float* qp = g_q + idx*QKD;
    const float* kp = g_k + idx*QKD;
    float qs = 0.f, ks = 0.f;
#pragma unroll
    for (int j = 0; j < QKD; j++) { qs = fmaf(qp[j], qp[j], qs); ks = fmaf(kp[j], kp[j], ks); }
    g_qn2[idx] = qs; g_kn2[idx] = ks;
}
__global__ void bound_qmax() {
    __shared__ float s[256];
    int b = blockIdx.x;
    float m = 0.f;
    for (int i = threadIdx.x; i < NN; i += 256) m = fmaxf(m, g_qn2[b*NN + i]);
    s[threadIdx.x] = m; __syncthreads();
    for (int st = 128; st > 0; st >>= 1) {
        if (threadIdx.x < st) s[threadIdx.x] = fmaxf(s[threadIdx.x], s[threadIdx.x + st]);
        __syncthreads();
    }
    if (threadIdx.x == 0) g_qmax[b] = s[0];
}
__global__ void bound_M() {
    int idx = blockIdx.x*256 + threadIdx.x;
    int b = idx >> 12;
    g_M[idx] = sqrtf(g_kn2[idx] * g_qmax[b]);
}

// ---------------- stats: logits(mma) -> exp -> S[n], store E fp16 -----------
#define EHS 136
__global__ void stats3() {
    extern __shared__ float sm[];
    float* ks  = sm;               // 128*40
    float* qs  = ks + 128*40;      // 64*40
    float* Mch = qs + 64*40;       // 128
    __half* Eh = (__half*)(Mch + 128);   // 64 x EHS halves

    int b = blockIdx.y, n0 = blockIdx.x*128;
    int tid = threadIdx.x, w = tid >> 5, lane = tid & 31, g = lane >> 2, tig = lane & 3;

#pragma unroll
    for (int r = 0; r < 16; r++) {
        int e = r*256 + tid; int row = e >> 5, col = e & 31;
        ks[row*40 + col] = tf32r(g_k[(b*NN + n0 + row)*QKD + col]);
    }
    if (tid < 128) Mch[tid] = g_M[b*NN + n0 + tid];
    __syncthreads();

    unsigned bb[2][4][2];
#pragma unroll
    for (int t = 0; t < 2; t++) {
        int nb = w*16 + t*8;
#pragma unroll
        for (int k4 = 0; k4 < 4; k4++) {
            int k0 = k4*8;
            bb[t][k4][0] = FU(ks[(nb + g)*40 + k0 + tig]);
            bb[t][k4][1] = FU(ks[(nb + g)*40 + k0 + tig + 4]);
        }
    }

    float scol[4] = {0.f, 0.f, 0.f, 0.f};
    for (int m0 = 0; m0 < NN; m0 += 64) {
        __syncthreads();
#pragma unroll
        for (int r = 0; r < 8; r++) {
            int e = r*256 + tid; int row = e >> 5, col = e & 31;
            qs[row*40 + col] = tf32r(g_q[(b*NN + m0 + row)*QKD + col]);
        }
        __syncthreads();
#pragma unroll
        for (int sw = 0; sw < 4; sw++) {
            unsigned a[4][4];
#pragma unroll
            for (int k4 = 0; k4 < 4; k4++) {
                int k0 = k4*8;
                a[k4][0] = FU(qs[(sw*16 + g)*40     + k0 + tig]);
                a[k4][1] = FU(qs[(sw*16 + 8 + g)*40 + k0 + tig]);
                a[k4][2] = FU(qs[(sw*16 + g)*40     + k0 + tig + 4]);
                a[k4][3] = FU(qs[(sw*16 + 8 + g)*40 + k0 + tig + 4]);
            }
#pragma unroll
            for (int t = 0; t < 2; t++) {
                float d[4] = {0.f, 0.f, 0.f, 0.f};
#pragma unroll
                for (int k4 = 0; k4 < 4; k4++)
                    mma8(d, a[k4][0], a[k4][1], a[k4][2], a[k4][3], bb[t][k4][0], bb[t][k4][1]);
                int nb = w*16 + t*8;
                float M0 = Mch[nb + 2*tig], M1 = Mch[nb + 2*tig + 1];
                float e0 = __expf(d[0] - M0), e1 = __expf(d[1] - M1);
                float e2 = __expf(d[2] - M0), e3 = __expf(d[3] - M1);
                scol[t*2]     += e0 + e2;
                scol[t*2 + 1] += e1 + e3;
                int col = nb + 2*tig;
                *(__half2*)(Eh + (sw*16 + g)*EHS     + col) = __floats2half2_rn(e0, e1);
                *(__half2*)(Eh + (sw*16 + 8 + g)*EHS + col) = __floats2half2_rn(e2, e3);
            }
        }
        __syncthreads();
        // copy staged E tile [64][128] -> g_E[b][m0+row][n0+col]
#pragma unroll
        for (int r = 0; r < 4; r++) {
            int e = r*256 + tid;           // 1024 uint4s
            int row = e >> 4, q4 = e & 15;
            uint4 val = *(const uint4*)(Eh + row*EHS + q4*8);
            *(uint4*)(g_E + ((size_t)(b*NN + m0 + row))*NN + n0 + q4*8) = val;
        }
    }
#pragma unroll
    for (int off = 16; off >= 4; off >>= 1)
#pragma unroll
        for (int i = 0; i < 4; i++)
            scol[i] += __shfl_down_sync(0xffffffffu, scol[i], off);
    if (lane < 4) {
#pragma unroll
        for (int t = 0; t < 2; t++)
#pragma unroll
            for (int p = 0; p < 2; p++) {
                int n = w*16 + t*8 + 2*lane + p;
                g_invS[b*NN + n0 + n] = 1.f / scol[t*2 + p];
            }
    }
}

// ---------------- vscale: g_vt[n][c] *= invS[n], tf32-round (in place) ------
__global__ void vscale_kernel() {
    int idx4 = blockIdx.x*256 + threadIdx.x;    // float4 index, BB*NN*CC/4
    int row = idx4 >> 6;
    float is = g_invS[row];
    float4 v = *((float4*)g_vt + idx4);
    v.x = tf32r(v.x * is); v.y = tf32r(v.y * is);
    v.z = tf32r(v.z * is); v.w = tf32r(v.w * is);
    *((float4*)g_vt + idx4) = v;
}

// ---------------- attnout: pure PV GEMM, M-tile 128, 512 threads ------------
__global__ void __launch_bounds__(512, 1) attnout3() {
    extern __shared__ float sm[];
    float* Es = sm;              // 128*40
    float* vs = Es + 128*40;     // 32*VSTR

    int b = blockIdx.y, m0 = blockIdx.x*128;
    int tid = threadIdx.x, w = tid >> 5, lane = tid & 31, g = lane >> 2, tig = lane & 3;
    int mw = w & 7, cw = w >> 3;

    float acc[16][4];
#pragma unroll
    for (int i = 0; i < 16; i++)
#pragma unroll
        for (int j = 0; j < 4; j++) acc[i][j] = 0.f;

    for (int n0 = 0; n0 < NN; n0 += 32) {
        __syncthreads();
#pragma unroll
        for (int r = 0; r < 4; r++) {            // E tile: 2048 uints (4096 halves)
            int e = r*512 + tid;
            int row = e >> 4, cp = e & 15;
            __half2 h = *(const __half2*)(g_E + ((size_t)(b*NN + m0 + row))*NN + n0 + cp*2);
            float2 f = __half22float2(h);
            Es[row*40 + cp*2]     = f.x;
            Es[row*40 + cp*2 + 1] = f.y;
        }
#pragma unroll
        for (int r = 0; r < 4; r++) {            // V tile: 2048 float4s
            int e = r*512 + tid;
            int row = e >> 6, c4 = e & 63;
            float4 v = *(const float4*)(g_vt + (size_t)(b*NN + n0 + row)*CC + c4*4);
            *(float4*)(vs + row*VSTR + c4*4) = v;
        }
        __syncthreads();
#pragma unroll
        for (int k4 = 0; k4 < 4; k4++) {
            int k0 = k4*8;
            unsigned a0 = FU(Es[(mw*16 + g)*40     + k0 + tig]);
            unsigned a1 = FU(Es[(mw*16 + 8 + g)*40 + k0 + tig]);
            unsigned a2 = FU(Es[(mw*16 + g)*40     + k0 + tig + 4]);
            unsigned a3 = FU(Es[(mw*16 + 8 + g)*40 + k0 + tig + 4]);
#pragma unroll
            for (int t8 = 0; t8 < 16; t8++) {
                int col = cw*128 + t8*8;
                unsigned b0 = FU(vs[(k0 + tig)*VSTR     + col + g]);
                unsigned b1 = FU(vs[(k0 + tig + 4)*VSTR + col + g]);
                mma8(acc[t8], a0, a1, a2, a3, b0, b1);
            }
        }
    }
    {
        int row = b*NN + m0 + mw*16 + g;
        float2* d0 = (float2*)(g_att + (size_t)row*CC);
        float2* d1 = (float2*)(g_att + (size_t)(row + 8)*CC);
#pragma unroll
        for (int t8 = 0; t8 < 16; t8++) {
            int cix = (cw*128 + t8*8 + 2*tig) >> 1;
            d0[cix] = make_float2(acc[t8][0], acc[t8][1]);
            d1[cix] = make_float2(acc[t8][2], acc[t8][3]);
        }
    }
}

// ---------------- MLP via mma: relu(X W1^T + b1) W2^T + b2 ------------------
__global__ void __launch_bounds__(256, 2) mlp_kernel2(const float* __restrict__ b1,
                                                      const float* __restrict__ b2) {
    extern __shared__ float sm[];
    float* Xs  = sm;              // 64*40
    float* W1s = Xs  + 64*40;     // 32*40
    float* Hs  = W1s + 32*40;     // 64*40
    float* W2s = Hs  + 64*40;     // 32*VSTR

    int m0 = blockIdx.x*64;
    int tid = threadIdx.x, w = tid >> 5, lane = tid & 31, g = lane >> 2, tig = lane & 3;
    int mw = w & 3, cw = w >> 2;
    int sw = w & 3, np = w >> 2;

    float acc2[16][4];
#pragma unroll
    for (int i = 0; i < 16; i++)
#pragma unroll
        for (int j = 0; j < 4; j++) acc2[i][j] = 0.f;

    for (int slab = 0; slab < 8; slab++) {
        float acc1[2][4];
#pragma unroll
        for (int t = 0; t < 2; t++)
#pragma unroll
            for (int j = 0; j < 4; j++) acc1[t][j] = 0.f;

        for (int kc = 0; kc < 8; kc++) {
            __syncthreads();
#pragma unroll
            for (int r = 0; r < 8; r++) {
                int e = r*256 + tid; int row = e >> 5, col = e & 31;
                Xs[row*40 + col] = tf32r(g_att[(size_t)(m0 + row)*CC + kc*32 + col]);
            }
#pragma unroll
            for (int r = 0; r < 4; r++) {
                int e = r*256 + tid; int row = e >> 5, col = e & 31;
                W1s[row*40 + col] = tf32r(g_W1t[(kc*32 + row)*CC + slab*32 + col]);
            }
            __syncthreads();
            unsigned a[4][4];
#pragma unroll
            for (int k4 = 0; k4 < 4; k4++) {
                int k0 = k4*8;
                a[k4][0] = FU(Xs[(sw*16 + g)*40     + k0 + tig]);
                a[k4][1] = FU(Xs[(sw*16 + 8 + g)*40 + k0 + tig]);
                a[k4][2] = FU(Xs[(sw*16 + g)*40     + k0 + tig + 4]);
                a[k4][3] = FU(Xs[(sw*16 + 8 + g)*40 + k0 + tig + 4]);
            }
#pragma unroll
            for (int t = 0; t < 2; t++) {
                int nb = np*16 + t*8;
#pragma unroll
                for (int k4 = 0; k4 < 4; k4++) {
                    int k0 = k4*8;
                    unsigned b0 = FU(W1s[(k0 + tig)*40     + nb + g]);
                    unsigned b1 = FU(W1s[(k0 + tig + 4)*40 + nb + g]);
                    mma8(acc1[t], a[k4][0], a[k4][1], a[k4][2], a[k4][3], b0, b1);
                }
            }
        }
#pragma unroll
        for (int t = 0; t < 2; t++) {
            int nb = np*16 + t*8;
            float bb0 = b1[slab*32 + nb + 2*tig];
            float bb1 = b1[slab*32 + nb + 2*tig + 1];
            Hs[(sw*16 + g)*40     + nb + 2*tig]     = tf32r(fmaxf(acc1[t][0] + bb0, 0.f));
            Hs[(sw*16 + g)*40     + nb + 2*tig + 1] = tf32r(fmaxf(acc1[t][1] + bb1, 0.f));
            Hs[(sw*16 + 8 + g)*40 + nb + 2*tig]     = tf32r(fmaxf(acc1[t][2] + bb0, 0.f));
            Hs[(sw*16 + 8 + g)*40 + nb + 2*tig + 1] = tf32r(fmaxf(acc1[t][3] + bb1, 0.f));
        }
#pragma unroll 8
        for (int r = 0; r < 32; r++)
            W2s[r*VSTR + tid] = tf32r(g_W2t[(slab*32 + r)*CC + tid]);
        __syncthreads();
#pragma unroll
        for (int k4 = 0; k4 < 4; k4++) {
            int k0 = k4*8;
            unsigned a0 = FU(Hs[(mw*16 + g)*40     + k0 + tig]);
            unsigned a1 = FU(Hs[(mw*16 + 8 + g)*40 + k0 + tig]);
            unsigned a2 = FU(Hs[(mw*16 + g)*40     + k0 + tig + 4]);
            unsigned a3 = FU(Hs[(mw*16 + 8 + g)*40 + k0 + tig + 4]);
#pragma unroll
            for (int t8 = 0; t8 < 16; t8++) {
                int col = cw*128 + t8*8;
                unsigned b0 = FU(W2s[(k0 + tig)*VSTR     + col + g]);
                unsigned b1 = FU(W2s[(k0 + tig + 4)*VSTR + col + g]);
                mma8(acc2[t8], a0, a1, a2, a3, b0, b1);
            }
        }
    }
    {
        int row = m0 + mw*16 + g;
#pragma unroll
        for (int t8 = 0; t8 < 16; t8++) {
            int col = cw*128 + t8*8 + 2*tig;
            g_mlp[(size_t)row*CC + col]           = acc2[t8][0] + b2[col];
            g_mlp[(size_t)row*CC + col + 1]       = acc2[t8][1] + b2[col + 1];
            g_mlp[(size_t)(row + 8)*CC + col]     = acc2[t8][2] + b2[col];
            g_mlp[(size_t)(row + 8)*CC + col + 1] = acc2[t8][3] + b2[col + 1];
        }
    }
}

// ---------------- LayerNorm ------------------------------------------------
__global__ void ln_partial() {
    __shared__ float ss[256], sq[256];
    int b = blockIdx.y, ch = blockIdx.x;
    const float* p = g_mlp + (size_t)b*NN*CC + ch*16384;
    float s = 0.f, q = 0.f;
#pragma unroll 8
    for (int r = 0; r < 64; r++) {
        float v = p[r*256 + threadIdx.x];
        s += v; q += v*v;
    }
    ss[threadIdx.x] = s; sq[threadIdx.x] = q;
    __syncthreads();
    for (int st = 128; st > 0; st >>= 1) {
        if (threadIdx.x < st) {
            ss[threadIdx.x] += ss[threadIdx.x + st];
            sq[threadIdx.x] += sq[threadIdx.x + st];
        }
        __syncthreads();
    }
    if (threadIdx.x == 0) {
        g_red[(b*64 + ch)*2 + 0] = ss[0];
        g_red[(b*64 + ch)*2 + 1] = sq[0];
    }
}

__global__ void ln_final() {
    __shared__ float ss[64], sq[64];
    int b = blockIdx.x, t = threadIdx.x;
    ss[t] = g_red[(b*64 + t)*2 + 0];
    sq[t] = g_red[(b*64 + t)*2 + 1];
    __syncthreads();
    for (int st = 32; st > 0; st >>= 1) {
        if (t < st) { ss[t] += ss[t + st]; sq[t] += sq[t + st]; }
        __syncthreads();
    }
    if (t == 0) {
        const float inv = 1.0f / (float)(NN * CC);
        float mean = ss[0] * inv;
        float var  = sq[0] * inv - mean*mean;
        g_mv[b*2 + 0] = mean;
        g_mv[b*2 + 1] = rsqrtf(var + 1e-5f);
    }
}

__global__ void ln_apply(const float* __restrict__ gamma,
                         const float* __restrict__ beta,
                         float* __restrict__ out) {
    __shared__ float s[32][33];
    int b = blockIdx.z, c0 = blockIdx.y*32, n0 = blockIdx.x*32;
    int tx = threadIdx.x, ty = threadIdx.y;
    float mean = g_mv[b*2], rstd = g_mv[b*2 + 1];
#pragma unroll
    for (int r = 0; r < 4; r++) {
        int n = n0 + ty + 8*r;
        s[ty + 8*r][tx] = g_mlp[(size_t)(b*NN + n)*CC + c0 + tx];
    }
    __syncthreads();
#pragma unroll
    for (int r = 0; r < 4; r++) {
        int c = c0 + ty + 8*r;
        int n = n0 + tx;
        float v = s[tx][ty + 8*r];
        size_t gi = (size_t)c*NN + n;
        out[(size_t)b*CC*NN + gi] = (v - mean)*rstd*gamma[gi] + beta[gi];
    }
}

// ---------------- launch ----------------------------------------------------
extern "C" void kernel_launch(void* const* d_in, const int* in_sizes, int n_in,
                              void* d_out, int out_size) {
    const float* x     = (const float*)d_in[0];
    const float* Wq    = (const float*)d_in[1];
    const float* bq    = (const float*)d_in[2];
    const float* Wk    = (const float*)d_in[3];
    const float* bk    = (const float*)d_in[4];
    const float* Wv    = (const float*)d_in[5];
    const float* bv    = (const float*)d_in[6];
    const float* W1    = (const float*)d_in[7];
    const float* b1    = (const float*)d_in[8];
    const float* W2    = (const float*)d_in[9];
    const float* b2    = (const float*)d_in[10];
    const float* gamma = (const float*)d_in[11];
    const float* beta  = (const float*)d_in[12];
    float* out = (float*)d_out;

    const int stats_smem = (128*40 + 64*40 + 128)*4 + 64*EHS*2;
    const int attn_smem  = (128*40 + 32*VSTR) * 4;
    const int mlp_smem   = (64*40 + 32*40 + 64*40 + 32*VSTR) * 4;
    cudaFuncSetAttribute(stats3,      cudaFuncAttributeMaxDynamicSharedMemorySize, stats_smem);
    cudaFuncSetAttribute(attnout3,    cudaFuncAttributeMaxDynamicSharedMemorySize, attn_smem);
    cudaFuncSetAttribute(mlp_kernel2, cudaFuncAttributeMaxDynamicSharedMemorySize, mlp_smem);

    wtrans_kernel<<<dim3(8, 8, 2), dim3(32, 8)>>>(W1, W2);
    qkv_mma<<<dim3(NN/64, 5, BB), 256>>>(x, Wq, bq, Wk, bk, Wv, bv);
    bound_norms<<<(BB*NN)/256, 256>>>();
    bound_qmax<<<BB, 256>>>();
    bound_M<<<(BB*NN)/256, 256>>>();
    stats3<<<dim3(NN/128, BB), 256, stats_smem>>>();
    vscale_kernel<<<(BB*NN*CC/4)/256, 256>>>();
    attnout3<<<dim3(NN/128, BB), 512, attn_smem>>>();
    mlp_kernel2<<<(BB*NN)/64, 256, mlp_smem>>>(b1, b2);
    ln_partial<<<dim3(64, BB), 256>>>();
    ln_final<<<BB, 64>>>();
    ln_apply<<<dim3(NN/32, CC/32, BB), dim3(32, 8)>>>(gamma, beta, out);
}

// round 7
// speedup vs baseline: 3.6608x; 1.3118x over previous
#include <cuda_runtime.h>
#include <cuda_fp16.h>
#include <math.h>

#define BB   8
#define CC   256
#define NN   4096
#define QKD  32
#define SCALE 0.17677669529663687f  /* 32^-0.5 */
#define EHS  136

// ---------------- scratch ---------------------------------------------------
__device__ float  g_q[BB*NN*QKD];
__device__ float  g_k[BB*NN*QKD];
__device__ float  g_vt[BB*NN*CC];            // [b][n][c] (+bv)
__device__ float  g_M[BB*NN];
__device__ float  g_invS[BB*NN];
__device__ __half g_E[(size_t)BB*NN*NN];     // E[b][m][n] fp16
__device__ __half g_vh[(size_t)BB*CC*NN];    // [b][c][n] fp16, pre-scaled by invS
__device__ float  g_att[BB*NN*CC];
__device__ float  g_mlp[BB*NN*CC];
__device__ __half g_W1h[CC*CC];              // [o][c] fp16
__device__ __half g_W2h[CC*CC];
__device__ float  g_qn2[BB*NN];
__device__ float  g_kn2[BB*NN];
__device__ float  g_qmax[BB];
__device__ float  g_red[BB*64*2];
__device__ float  g_mv[BB*2];

// ---------------- helpers ----------------------------------------------------
__device__ __forceinline__ float tf32r(float x) {
    unsigned u;
    asm("cvt.rna.tf32.f32 %0, %1;" : "=r"(u) : "f"(x));
    return __uint_as_float(u);
}
__device__ __forceinline__ void mma8(float* c,
                                     unsigned a0, unsigned a1, unsigned a2, unsigned a3,
                                     unsigned b0, unsigned b1) {
    asm volatile("mma.sync.aligned.m16n8k8.row.col.f32.tf32.tf32.f32 "
                 "{%0,%1,%2,%3}, {%4,%5,%6,%7}, {%8,%9}, {%0,%1,%2,%3};\n"
                 : "+f"(c[0]), "+f"(c[1]), "+f"(c[2]), "+f"(c[3])
                 : "r"(a0), "r"(a1), "r"(a2), "r"(a3), "r"(b0), "r"(b1));
}
__device__ __forceinline__ void mma16(float* c,
                                      unsigned a0, unsigned a1, unsigned a2, unsigned a3,
                                      unsigned b0, unsigned b1) {
    asm volatile("mma.sync.aligned.m16n8k16.row.col.f32.f16.f16.f32 "
                 "{%0,%1,%2,%3}, {%4,%5,%6,%7}, {%8,%9}, {%0,%1,%2,%3};\n"
                 : "+f"(c[0]), "+f"(c[1]), "+f"(c[2]), "+f"(c[3])
                 : "r"(a0), "r"(a1), "r"(a2), "r"(a3), "r"(b0), "r"(b1));
}
#define FU  __float_as_uint
#define LH2(p) (*(const unsigned*)(p))

// ---------------- weight prep: W1/W2 -> fp16 [o][c] --------------------------
__global__ void wprep(const float* __restrict__ W1, const float* __restrict__ W2) {
    int i = blockIdx.x*256 + threadIdx.x;
    if (i < CC*CC) g_W1h[i] = __float2half(W1[i]);
    else           g_W2h[i - CC*CC] = __float2half(W2[i - CC*CC]);
}

// ---------------- q/k/v projection via tf32 mma ------------------------------
#define XS 72
__global__ void qkv_mma(const float* __restrict__ x,
                        const float* __restrict__ Wq, const float* __restrict__ bq,
                        const float* __restrict__ Wk, const float* __restrict__ bk,
                        const float* __restrict__ Wv, const float* __restrict__ bv) {
    __shared__ float xs[32*XS];
    __shared__ float ws[64*40];
    int b  = blockIdx.z;
    int o0 = blockIdx.y * 64;
    int n0 = blockIdx.x * 64;
    int tid = threadIdx.x, w = tid >> 5, lane = tid & 31, g = lane >> 2, tig = lane & 3;
    int sw = w & 3, np = w >> 2;
    const float* xb = x + (size_t)b * CC * NN;

    float acc[4][4];
#pragma unroll
    for (int i = 0; i < 4; i++)
#pragma unroll
        for (int j = 0; j < 4; j++) acc[i][j] = 0.f;

    for (int c0 = 0; c0 < CC; c0 += 32) {
        __syncthreads();
#pragma unroll
        for (int r = 0; r < 8; r++) {
            int e = r*256 + tid; int cc = e >> 6, nn = e & 63;
            xs[cc*XS + nn] = tf32r(xb[(c0 + cc)*NN + n0 + nn]);
        }
#pragma unroll
        for (int r = 0; r < 8; r++) {
            int e = r*256 + tid; int oo = e >> 5, cc = e & 31;
            int o = o0 + oo;
            const float* Wr = (o < 32) ? (Wq + o*CC)
                            : (o < 64) ? (Wk + (o-32)*CC)
                                       : (Wv + (o-64)*CC);
            ws[oo*40 + cc] = tf32r(Wr[c0 + cc]);
        }
        __syncthreads();
#pragma unroll
        for (int k4 = 0; k4 < 4; k4++) {
            int k0 = k4*8;
            unsigned a0 = FU(xs[(k0 + tig)*XS     + sw*16 + g]);
            unsigned a1 = FU(xs[(k0 + tig)*XS     + sw*16 + 8 + g]);
            unsigned a2 = FU(xs[(k0 + tig + 4)*XS + sw*16 + g]);
            unsigned a3 = FU(xs[(k0 + tig + 4)*XS + sw*16 + 8 + g]);
#pragma unroll
            for (int t8 = 0; t8 < 4; t8++) {
                int oc = np*32 + t8*8 + g;
                unsigned b0 = FU(ws[oc*40 + k0 + tig]);
                unsigned b1 = FU(ws[oc*40 + k0 + tig + 4]);
                mma8(acc[t8], a0, a1, a2, a3, b0, b1);
            }
        }
    }
#pragma unroll
    for (int t8 = 0; t8 < 4; t8++) {
#pragma unroll
        for (int rr = 0; rr < 2; rr++) {
#pragma unroll
            for (int cc = 0; cc < 2; cc++) {
                int n = n0 + sw*16 + g + rr*8;
                int o = o0 + np*32 + t8*8 + 2*tig + cc;
                float v = acc[t8][rr*2 + cc];
                if (o < 32)       g_q[(b*NN + n)*QKD + o]        = (v + __ldg(bq + o)) * SCALE;
                else if (o < 64)  g_k[(b*NN + n)*QKD + (o - 32)] = v + __ldg(bk + o - 32);
                else              g_vt[(size_t)(b*NN + n)*CC + (o - 64)] = v + __ldg(bv + o - 64);
            }
        }
    }
}

// ---------------- softmax shift: M'[b][n] = ||k_n|| * max_m ||q_m|| ---------
__global__ void bound_norms() {
    int idx = blockIdx.x*256 + threadIdx.x;
    const float* qp = g_q + idx*QKD;
    const float* kp = g_k + idx*QKD;
    float qs = 0.f, ks = 0.f;
#pragma unroll
    for (int j = 0; j < QKD; j++) { qs = fmaf(qp[j], qp[j], qs); ks = fmaf(kp[j], kp[j], ks); }
    g_qn2[idx] = qs; g_kn2[idx] = ks;
}
__global__ void bound_qmax() {
    __shared__ float s[256];
    int b = blockIdx.x;
    float m = 0.f;
    for (int i = threadIdx.x; i < NN; i += 256) m = fmaxf(m, g_qn2[b*NN + i]);
    s[threadIdx.x] = m; __syncthreads();
    for (int st = 128; st > 0; st >>= 1) {
        if (threadIdx.x < st) s[threadIdx.x] = fmaxf(s[threadIdx.x], s[threadIdx.x + st]);
        __syncthreads();
    }
    if (threadIdx.x == 0) g_qmax[b] = s[0];
}
__global__ void bound_M() {
    int idx = blockIdx.x*256 + threadIdx.x;
    int b = idx >> 12;
    g_M[idx] = sqrtf(g_kn2[idx] * g_qmax[b]);
}

// ---------------- stats: logits(fp16 mma) -> exp -> S[n], store E fp16 ------
__global__ void stats4() {
    extern __shared__ char smc[];
    float*  Mch = (float*)smc;                 // 128
    __half* ks  = (__half*)(smc + 512);        // 128*40
    __half* qs  = (__half*)(smc + 10752);      // 64*40
    __half* Eh  = (__half*)(smc + 15872);      // 64*EHS

    int b = blockIdx.y, n0 = blockIdx.x*128;
    int tid = threadIdx.x, w = tid >> 5, lane = tid & 31, g = lane >> 2, tig = lane & 3;

#pragma unroll
    for (int r = 0; r < 8; r++) {
        int e = r*256 + tid; int row = e >> 4, c2 = e & 15;
        float2 f = *(const float2*)(g_k + (b*NN + n0 + row)*QKD + 2*c2);
        *(__half2*)(ks + row*40 + 2*c2) = __floats2half2_rn(f.x, f.y);
    }
    if (tid < 128) Mch[tid] = g_M[b*NN + n0 + tid];
    __syncthreads();

    unsigned bb[2][2][2];
#pragma unroll
    for (int t = 0; t < 2; t++) {
        int nb = w*16 + t*8;
#pragma unroll
        for (int k2 = 0; k2 < 2; k2++) {
            const __half* p = ks + (nb + g)*40 + k2*16 + 2*tig;
            bb[t][k2][0] = LH2(p);
            bb[t][k2][1] = LH2(p + 8);
        }
    }

    float scol[4] = {0.f, 0.f, 0.f, 0.f};
    for (int m0 = 0; m0 < NN; m0 += 64) {
        __syncthreads();
#pragma unroll
        for (int r = 0; r < 4; r++) {
            int e = r*256 + tid; int row = e >> 4, c2 = e & 15;
            float2 f = *(const float2*)(g_q + (b*NN + m0 + row)*QKD + 2*c2);
            *(__half2*)(qs + row*40 + 2*c2) = __floats2half2_rn(f.x, f.y);
        }
        __syncthreads();
#pragma unroll
        for (int sw = 0; sw < 4; sw++) {
            unsigned a[2][4];
#pragma unroll
            for (int k2 = 0; k2 < 2; k2++) {
                const __half* p = qs + (sw*16 + g)*40 + k2*16 + 2*tig;
                a[k2][0] = LH2(p);
                a[k2][1] = LH2(p + 8*40);
                a[k2][2] = LH2(p + 8);
                a[k2][3] = LH2(p + 8*40 + 8);
            }
#pragma unroll
            for (int t = 0; t < 2; t++) {
                float d[4] = {0.f, 0.f, 0.f, 0.f};
#pragma unroll
                for (int k2 = 0; k2 < 2; k2++)
                    mma16(d, a[k2][0], a[k2][1], a[k2][2], a[k2][3],
                          bb[t][k2][0], bb[t][k2][1]);
                int nb = w*16 + t*8;
                float M0 = Mch[nb + 2*tig], M1 = Mch[nb + 2*tig + 1];
                float e0 = __expf(d[0] - M0), e1 = __expf(d[1] - M1);
                float e2 = __expf(d[2] - M0), e3 = __expf(d[3] - M1);
                scol[t*2]     += e0 + e2;
                scol[t*2 + 1] += e1 + e3;
                int col = nb + 2*tig;
                *(__half2*)(Eh + (sw*16 + g)*EHS     + col) = __floats2half2_rn(e0, e1);
                *(__half2*)(Eh + (sw*16 + 8 + g)*EHS + col) = __floats2half2_rn(e2, e3);
            }
        }
        __syncthreads();
#pragma unroll
        for (int r = 0; r < 4; r++) {
            int e = r*256 + tid;
            int row = e >> 4, q4 = e & 15;
            uint4 val = *(const uint4*)(Eh + row*EHS + q4*8);
            *(uint4*)(g_E + ((size_t)(b*NN + m0 + row))*NN + n0 + q4*8) = val;
        }
    }
#pragma unroll
    for (int off = 16; off >= 4; off >>= 1)
#pragma unroll
        for (int i = 0; i < 4; i++)
            scol[i] += __shfl_down_sync(0xffffffffu, scol[i], off);
    if (lane < 4) {
#pragma unroll
        for (int t = 0; t < 2; t++)
#pragma unroll
            for (int p = 0; p < 2; p++) {
                int n = w*16 + t*8 + 2*lane + p;
                g_invS[b*NN + n0 + n] = 1.f / scol[t*2 + p];
            }
    }
}

// ---------------- vprep: g_vh[b][c][n] = half(v[n][c] * invS[n]) -------------
__global__ void vprep() {
    __shared__ float s[32][33];
    int b = blockIdx.z, c0 = blockIdx.y*32, n0 = blockIdx.x*32;
    int tx = threadIdx.x, ty = threadIdx.y;
#pragma unroll
    for (int r = 0; r < 4; r++) {
        int n = n0 + ty + 8*r;
        s[ty + 8*r][tx] = g_vt[(size_t)(b*NN + n)*CC + c0 + tx] * g_invS[b*NN + n];
    }
    __syncthreads();
#pragma unroll
    for (int r = 0; r < 4; r++) {
        int c = c0 + ty + 8*r;
        g_vh[((size_t)b*CC + c)*NN + n0 + tx] = __float2half(s[tx][ty + 8*r]);
    }
}

// ---------------- attnout: fp16 PV GEMM, 128m tile, 512 threads --------------
__global__ void __launch_bounds__(512) attnout4() {
    extern __shared__ __half smh[];
    __half* Es  = smh;             // 128*40
    __half* vsT = smh + 128*40;    // 256*40

    int b = blockIdx.y, m0 = blockIdx.x*128;
    int tid = threadIdx.x, w = tid >> 5, lane = tid & 31, g = lane >> 2, tig = lane & 3;
    int mw = w & 3, cw = w >> 2;   // m = mw*32, col = cw*64

    float acc[2][8][4];
#pragma unroll
    for (int ms = 0; ms < 2; ms++)
#pragma unroll
        for (int i = 0; i < 8; i++)
#pragma unroll
            for (int j = 0; j < 4; j++) acc[ms][i][j] = 0.f;

    for (int n0 = 0; n0 < NN; n0 += 32) {
        __syncthreads();
#pragma unroll
        for (int r = 0; r < 4; r++) {
            int e = r*512 + tid; int row = e >> 4, c2 = e & 15;
            *(__half2*)(Es + row*40 + 2*c2) =
                *(const __half2*)(g_E + ((size_t)(b*NN + m0 + row))*NN + n0 + 2*c2);
        }
#pragma unroll
        for (int r = 0; r < 8; r++) {
            int e = r*512 + tid; int row = e >> 4, c2 = e & 15;
            *(__half2*)(vsT + row*40 + 2*c2) =
                *(const __half2*)(g_vh + ((size_t)b*CC + row)*NN + n0 + 2*c2);
        }
        __syncthreads();
#pragma unroll
        for (int k2 = 0; k2 < 2; k2++) {
            unsigned a[2][4];
#pragma unroll
            for (int ms = 0; ms < 2; ms++) {
                const __half* p = Es + (mw*32 + ms*16 + g)*40 + k2*16 + 2*tig;
                a[ms][0] = LH2(p);
                a[ms][1] = LH2(p + 8*40);
                a[ms][2] = LH2(p + 8);
                a[ms][3] = LH2(p + 8*40 + 8);
            }
#pragma unroll
            for (int t8 = 0; t8 < 8; t8++) {
                const __half* bp = vsT + (cw*64 + t8*8 + g)*40 + k2*16 + 2*tig;
                unsigned b0 = LH2(bp);
                unsigned b1 = LH2(bp + 8);
#pragma unroll
                for (int ms = 0; ms < 2; ms++)
                    mma16(acc[ms][t8], a[ms][0], a[ms][1], a[ms][2], a[ms][3], b0, b1);
            }
        }
    }
#pragma unroll
    for (int ms = 0; ms < 2; ms++) {
        int row = b*NN + m0 + mw*32 + ms*16 + g;
        float2* d0 = (float2*)(g_att + (size_t)row*CC);
        float2* d1 = (float2*)(g_att + (size_t)(row + 8)*CC);
#pragma unroll
        for (int t8 = 0; t8 < 8; t8++) {
            int cix = (cw*64 + t8*8 + 2*tig) >> 1;
            d0[cix] = make_float2(acc[ms][t8][0], acc[ms][t8][1]);
            d1[cix] = make_float2(acc[ms][t8][2], acc[ms][t8][3]);
        }
    }
}

// ---------------- MLP fp16: relu(X W1^T + b1) W2^T + b2 + LN partials --------
__global__ void __launch_bounds__(256, 2) mlp4(const float* __restrict__ b1,
                                               const float* __restrict__ b2) {
    extern __shared__ __half smh[];
    __half* Xs  = smh;                   // 64*264
    __half* W1s = Xs  + 64*264;          // 32*264
    __half* Hs  = W1s + 32*264;          // 64*40
    __half* W2s = Hs  + 64*40;           // 256*40

    int m0 = blockIdx.x*64;
    int tid = threadIdx.x, w = tid >> 5, lane = tid & 31, g = lane >> 2, tig = lane & 3;
    int sw = w & 3, np = w >> 2;   // GEMM1 roles
    int m2 = w & 1, c4 = w >> 1;   // GEMM2 roles: m = m2*32, col = c4*64

    // load whole X tile (64 x 256) as fp16
#pragma unroll
    for (int r = 0; r < 32; r++) {
        int e = r*256 + tid; int row = e >> 7, c2 = e & 127;
        float2 f = *(const float2*)(g_att + (size_t)(m0 + row)*CC + 2*c2);
        *(__half2*)(Xs + row*264 + 2*c2) = __floats2half2_rn(f.x, f.y);
    }

    float acc2[2][8][4];
#pragma unroll
    for (int ms = 0; ms < 2; ms++)
#pragma unroll
        for (int i = 0; i < 8; i++)
#pragma unroll
            for (int j = 0; j < 4; j++) acc2[ms][i][j] = 0.f;

    for (int slab = 0; slab < 8; slab++) {
        __syncthreads();
#pragma unroll
        for (int r = 0; r < 16; r++) {
            int e = r*256 + tid; int row = e >> 7, c2 = e & 127;
            *(__half2*)(W1s + row*264 + 2*c2) =
                *(const __half2*)(g_W1h + (slab*32 + row)*CC + 2*c2);
        }
#pragma unroll
        for (int r = 0; r < 16; r++) {
            int e = r*256 + tid; int row = e >> 4, c2 = e & 15;
            *(__half2*)(W2s + row*40 + 2*c2) =
                *(const __half2*)(g_W2h + row*CC + slab*32 + 2*c2);
        }
        __syncthreads();
        // GEMM1: H_slab[64 x 32] = X @ W1_slab^T
        float acc1[2][4];
#pragma unroll
        for (int t = 0; t < 2; t++)
#pragma unroll
            for (int j = 0; j < 4; j++) acc1[t][j] = 0.f;
#pragma unroll
        for (int k2 = 0; k2 < 16; k2++) {
            const __half* p = Xs + (sw*16 + g)*264 + k2*16 + 2*tig;
            unsigned a0 = LH2(p);
            unsigned a1 = LH2(p + 8*264);
            unsigned a2 = LH2(p + 8);
            unsigned a3 = LH2(p + 8*264 + 8);
#pragma unroll
            for (int t = 0; t < 2; t++) {
                const __half* bp = W1s + (np*16 + t*8 + g)*264 + k2*16 + 2*tig;
                mma16(acc1[t], a0, a1, a2, a3, LH2(bp), LH2(bp + 8));
            }
        }
        // relu + bias -> Hs (fp16)
#pragma unroll
        for (int t = 0; t < 2; t++) {
            int nb = np*16 + t*8;
            float bb0 = b1[slab*32 + nb + 2*tig];
            float bb1 = b1[slab*32 + nb + 2*tig + 1];
            *(__half2*)(Hs + (sw*16 + g)*40 + nb + 2*tig) =
                __floats2half2_rn(fmaxf(acc1[t][0] + bb0, 0.f), fmaxf(acc1[t][1] + bb1, 0.f));
            *(__half2*)(Hs + (sw*16 + 8 + g)*40 + nb + 2*tig) =
                __floats2half2_rn(fmaxf(acc1[t][2] + bb0, 0.f), fmaxf(acc1[t][3] + bb1, 0.f));
        }
        __syncthreads();
        // GEMM2 partial: acc2 += H_slab @ W2_slab^T
#pragma unroll
        for (int k2 = 0; k2 < 2; k2++) {
            unsigned a[2][4];
#pragma unroll
            for (int ms = 0; ms < 2; ms++) {
                const __half* p = Hs + (m2*32 + ms*16 + g)*40 + k2*16 + 2*tig;
                a[ms][0] = LH2(p);
                a[ms][1] = LH2(p + 8*40);
                a[ms][2] = LH2(p + 8);
                a[ms][3] = LH2(p + 8*40 + 8);
            }
#pragma unroll
            for (int t8 = 0; t8 < 8; t8++) {
                const __half* bp = W2s + (c4*64 + t8*8 + g)*40 + k2*16 + 2*tig;
                unsigned b0 = LH2(bp);
                unsigned b1 = LH2(bp + 8);
#pragma unroll
                for (int ms = 0; ms < 2; ms++)
                    mma16(acc2[ms][t8], a[ms][0], a[ms][1], a[ms][2], a[ms][3], b0, b1);
            }
        }
    }
    // epilogue + b2 + LN block partials
    float bs = 0.f, bqq = 0.f;
#pragma unroll
    for (int ms = 0; ms < 2; ms++) {
        int row = m0 + m2*32 + ms*16 + g;
#pragma unroll
        for (int t8 = 0; t8 < 8; t8++) {
            int col = c4*64 + t8*8 + 2*tig;
            float v0 = acc2[ms][t8][0] + b2[col];
            float v1 = acc2[ms][t8][1] + b2[col + 1];
            float v2 = acc2[ms][t8][2] + b2[col];
            float v3 = acc2[ms][t8][3] + b2[col + 1];
            *(float2*)(g_mlp + (size_t)row*CC + col)       = make_float2(v0, v1);
            *(float2*)(g_mlp + (size_t)(row + 8)*CC + col) = make_float2(v2, v3);
            bs  += v0 + v1 + v2 + v3;
            bqq += v0*v0 + v1*v1 + v2*v2 + v3*v3;
        }
    }
    __syncthreads();
    float* red = (float*)smh;
    red[tid] = bs; red[256 + tid] = bqq;
    __syncthreads();
    for (int st = 128; st > 0; st >>= 1) {
        if (tid < st) { red[tid] += red[tid + st]; red[256 + tid] += red[256 + tid + st]; }
        __syncthreads();
    }
    if (tid == 0) {
        g_red[blockIdx.x*2 + 0] = red[0];
        g_red[blockIdx.x*2 + 1] = red[256];
    }
}

// ---------------- LayerNorm --------------------------------------------------
__global__ void ln_final() {
    __shared__ float ss[64], sq[64];
    int b = blockIdx.x, t = threadIdx.x;
    ss[t] = g_red[(b*64 + t)*2 + 0];
    sq[t] = g_red[(b*64 + t)*2 + 1];
    __syncthreads();
    for (int st = 32; st > 0; st >>= 1) {
        if (t < st) { ss[t] += ss[t + st]; sq[t] += sq[t + st]; }
        __syncthreads();
    }
    if (t == 0) {
        const float inv = 1.0f / (float)(NN * CC);
        float mean = ss[0] * inv;
        float var  = sq[0] * inv - mean*mean;
        g_mv[b*2 + 0] = mean;
        g_mv[b*2 + 1] = rsqrtf(var + 1e-5f);
    }
}

__global__ void ln_apply(const float* __restrict__ gamma,
                         const float* __restrict__ beta,
                         float* __restrict__ out) {
    __shared__ float s[32][33];
    int b = blockIdx.z, c0 = blockIdx.y*32, n0 = blockIdx.x*32;
    int tx = threadIdx.x, ty = threadIdx.y;
    float mean = g_mv[b*2], rstd = g_mv[b*2 + 1];
#pragma unroll
    for (int r = 0; r < 4; r++) {
        int n = n0 + ty + 8*r;
        s[ty + 8*r][tx] = g_mlp[(size_t)(b*NN + n)*CC + c0 + tx];
    }
    __syncthreads();
#pragma unroll
    for (int r = 0; r < 4; r++) {
        int c = c0 + ty + 8*r;
        int n = n0 + tx;
        float v = s[tx][ty + 8*r];
        size_t gi = (size_t)c*NN + n;
        out[(size_t)b*CC*NN + gi] = (v - mean)*rstd*gamma[gi] + beta[gi];
    }
}

// ---------------- launch ----------------------------------------------------
extern "C" void kernel_launch(void* const* d_in, const int* in_sizes, int n_in,
                              void* d_out, int out_size) {
    const float* x     = (const float*)d_in[0];
    const float* Wq    = (const float*)d_in[1];
    const float* bq    = (const float*)d_in[2];
    const float* Wk    = (const float*)d_in[3];
    const float* bk    = (const float*)d_in[4];
    const float* Wv    = (const float*)d_in[5];
    const float* bv    = (const float*)d_in[6];
    const float* W1    = (const float*)d_in[7];
    const float* b1    = (const float*)d_in[8];
    const float* W2    = (const float*)d_in[9];
    const float* b2    = (const float*)d_in[10];
    const float* gamma = (const float*)d_in[11];
    const float* beta  = (const float*)d_in[12];
    float* out = (float*)d_out;

    const int stats_smem = 512 + (128*40 + 64*40 + 64*EHS)*2;     // 33280
    const int attn_smem  = (128*40 + 256*40)*2;                   // 30720
    const int mlp_smem   = (64*264 + 32*264 + 64*40 + 256*40)*2;  // 76288
    cudaFuncSetAttribute(stats4,   cudaFuncAttributeMaxDynamicSharedMemorySize, stats_smem);
    cudaFuncSetAttribute(attnout4, cudaFuncAttributeMaxDynamicSharedMemorySize, attn_smem);
    cudaFuncSetAttribute(mlp4,     cudaFuncAttributeMaxDynamicSharedMemorySize, mlp_smem);

    wprep<<<(2*CC*CC)/256, 256>>>(W1, W2);
    qkv_mma<<<dim3(NN/64, 5, BB), 256>>>(x, Wq, bq, Wk, bk, Wv, bv);
    bound_norms<<<(BB*NN)/256, 256>>>();
    bound_qmax<<<BB, 256>>>();
    bound_M<<<(BB*NN)/256, 256>>>();
    stats4<<<dim3(NN/128, BB), 256, stats_smem>>>();
    vprep<<<dim3(NN/32, CC/32, BB), dim3(32, 8)>>>();
    attnout4<<<dim3(NN/128, BB), 512, attn_smem>>>();
    mlp4<<<(BB*NN)/64, 256, mlp_smem>>>(b1, b2);
    ln_final<<<BB, 64>>>();
    ln_apply<<<dim3(NN/32, CC/32, BB), dim3(32, 8)>>>(gamma, beta, out);
}

// round 8
// speedup vs baseline: 5.0479x; 1.3789x over previous
#include <cuda_runtime.h>
#include <cuda_fp16.h>
#include <math.h>

#define BB   8
#define CC   256
#define NN   4096
#define QKD  32
#define SCALE 0.17677669529663687f  /* 32^-0.5 */
#define EHS  136

// ---------------- scratch ---------------------------------------------------
__device__ float  g_q[BB*NN*QKD];
__device__ float  g_k[BB*NN*QKD];
__device__ float  g_vt[BB*NN*CC];            // [b][n][c] (+bv)
__device__ float  g_M[BB*NN];
__device__ float  g_invS[BB*NN];
__device__ __align__(16) __half g_E[(size_t)BB*NN*NN];   // E[b][m][n] fp16
__device__ __align__(16) __half g_vh[(size_t)BB*CC*NN];  // [b][c][n] fp16, *invS
__device__ __align__(16) __half g_xh[(size_t)BB*NN*CC];  // attention out fp16 [m][c]
__device__ float  g_mlp[BB*NN*CC];
__device__ __half g_W1h[CC*CC];              // [o][c] fp16
__device__ __half g_W2h[CC*CC];
__device__ float  g_qn2[BB*NN];
__device__ float  g_kn2[BB*NN];
__device__ float  g_qmax[BB];
__device__ float  g_red[BB*64*2];
__device__ float  g_mv[BB*2];

// ---------------- helpers ----------------------------------------------------
__device__ __forceinline__ float tf32r(float x) {
    unsigned u;
    asm("cvt.rna.tf32.f32 %0, %1;" : "=r"(u) : "f"(x));
    return __uint_as_float(u);
}
__device__ __forceinline__ void mma8(float* c,
                                     unsigned a0, unsigned a1, unsigned a2, unsigned a3,
                                     unsigned b0, unsigned b1) {
    asm volatile("mma.sync.aligned.m16n8k8.row.col.f32.tf32.tf32.f32 "
                 "{%0,%1,%2,%3}, {%4,%5,%6,%7}, {%8,%9}, {%0,%1,%2,%3};\n"
                 : "+f"(c[0]), "+f"(c[1]), "+f"(c[2]), "+f"(c[3])
                 : "r"(a0), "r"(a1), "r"(a2), "r"(a3), "r"(b0), "r"(b1));
}
__device__ __forceinline__ void mma16(float* c,
                                      unsigned a0, unsigned a1, unsigned a2, unsigned a3,
                                      unsigned b0, unsigned b1) {
    asm volatile("mma.sync.aligned.m16n8k16.row.col.f32.f16.f16.f32 "
                 "{%0,%1,%2,%3}, {%4,%5,%6,%7}, {%8,%9}, {%0,%1,%2,%3};\n"
                 : "+f"(c[0]), "+f"(c[1]), "+f"(c[2]), "+f"(c[3])
                 : "r"(a0), "r"(a1), "r"(a2), "r"(a3), "r"(b0), "r"(b1));
}
#define FU  __float_as_uint
#define LH2(p) (*(const unsigned*)(p))
#define CPA(dst, src)  asm volatile("cp.async.cg.shared.global [%0], [%1], 16;\n" :: "r"(dst), "l"(src))
#define CPCOMMIT()     asm volatile("cp.async.commit_group;\n")
#define CPWAIT1()      asm volatile("cp.async.wait_group 1;\n" ::: "memory")
#define CPWAIT0()      asm volatile("cp.async.wait_group 0;\n" ::: "memory")
#define LDSM4(r0,r1,r2,r3,addr) \
    asm volatile("ldmatrix.sync.aligned.m8n8.x4.shared.b16 {%0,%1,%2,%3}, [%4];" \
                 : "=r"(r0), "=r"(r1), "=r"(r2), "=r"(r3) : "r"(addr))

__device__ __forceinline__ unsigned s2u(const void* p) {
    unsigned a;
    asm("{ .reg .u64 t; cvta.to.shared.u64 t, %1; cvt.u32.u64 %0, t; }" : "=r"(a) : "l"(p));
    return a;
}

// ---------------- weight prep: W1/W2 -> fp16 [o][c] --------------------------
__global__ void wprep(const float* __restrict__ W1, const float* __restrict__ W2) {
    int i = blockIdx.x*256 + threadIdx.x;
    if (i < CC*CC) g_W1h[i] = __float2half(W1[i]);
    else           g_W2h[i - CC*CC] = __float2half(W2[i - CC*CC]);
}

// ---------------- q/k/v projection via tf32 mma ------------------------------
#define XS 72
__global__ void qkv_mma(const float* __restrict__ x,
                        const float* __restrict__ Wq, const float* __restrict__ bq,
                        const float* __restrict__ Wk, const float* __restrict__ bk,
                        const float* __restrict__ Wv, const float* __restrict__ bv) {
    __shared__ float xs[32*XS];
    __shared__ float ws[64*40];
    int b  = blockIdx.z;
    int o0 = blockIdx.y * 64;
    int n0 = blockIdx.x * 64;
    int tid = threadIdx.x, w = tid >> 5, lane = tid & 31, g = lane >> 2, tig = lane & 3;
    int sw = w & 3, np = w >> 2;
    const float* xb = x + (size_t)b * CC * NN;

    float acc[4][4];
#pragma unroll
    for (int i = 0; i < 4; i++)
#pragma unroll
        for (int j = 0; j < 4; j++) acc[i][j] = 0.f;

    for (int c0 = 0; c0 < CC; c0 += 32) {
        __syncthreads();
#pragma unroll
        for (int r = 0; r < 8; r++) {
            int e = r*256 + tid; int cc = e >> 6, nn = e & 63;
            xs[cc*XS + nn] = tf32r(xb[(c0 + cc)*NN + n0 + nn]);
        }
#pragma unroll
        for (int r = 0; r < 8; r++) {
            int e = r*256 + tid; int oo = e >> 5, cc = e & 31;
            int o = o0 + oo;
            const float* Wr = (o < 32) ? (Wq + o*CC)
                            : (o < 64) ? (Wk + (o-32)*CC)
                                       : (Wv + (o-64)*CC);
            ws[oo*40 + cc] = tf32r(Wr[c0 + cc]);
        }
        __syncthreads();
#pragma unroll
        for (int k4 = 0; k4 < 4; k4++) {
            int k0 = k4*8;
            unsigned a0 = FU(xs[(k0 + tig)*XS     + sw*16 + g]);
            unsigned a1 = FU(xs[(k0 + tig)*XS     + sw*16 + 8 + g]);
            unsigned a2 = FU(xs[(k0 + tig + 4)*XS + sw*16 + g]);
            unsigned a3 = FU(xs[(k0 + tig + 4)*XS + sw*16 + 8 + g]);
#pragma unroll
            for (int t8 = 0; t8 < 4; t8++) {
                int oc = np*32 + t8*8 + g;
                unsigned b0 = FU(ws[oc*40 + k0 + tig]);
                unsigned b1 = FU(ws[oc*40 + k0 + tig + 4]);
                mma8(acc[t8], a0, a1, a2, a3, b0, b1);
            }
        }
    }
#pragma unroll
    for (int t8 = 0; t8 < 4; t8++) {
#pragma unroll
        for (int rr = 0; rr < 2; rr++) {
#pragma unroll
            for (int cc = 0; cc < 2; cc++) {
                int n = n0 + sw*16 + g + rr*8;
                int o = o0 + np*32 + t8*8 + 2*tig + cc;
                float v = acc[t8][rr*2 + cc];
                if (o < 32)       g_q[(b*NN + n)*QKD + o]        = (v + __ldg(bq + o)) * SCALE;
                else if (o < 64)  g_k[(b*NN + n)*QKD + (o - 32)] = v + __ldg(bk + o - 32);
                else              g_vt[(size_t)(b*NN + n)*CC + (o - 64)] = v + __ldg(bv + o - 64);
            }
        }
    }
}

// ---------------- softmax shift: M'[b][n] = ||k_n|| * max_m ||q_m|| ---------
__global__ void bound_norms() {
    int idx = blockIdx.x*256 + threadIdx.x;
    const float* qp = g_q + idx*QKD;
    const float* kp = g_k + idx*QKD;
    float qs = 0.f, ks = 0.f;
#pragma unroll
    for (int j = 0; j < QKD; j++) { qs = fmaf(qp[j], qp[j], qs); ks = fmaf(kp[j], kp[j], ks); }
    g_qn2[idx] = qs; g_kn2[idx] = ks;
}
__global__ void bound_qmax() {
    __shared__ float s[256];
    int b = blockIdx.x;
    float m = 0.f;
    for (int i = threadIdx.x; i < NN; i += 256) m = fmaxf(m, g_qn2[b*NN + i]);
    s[threadIdx.x] = m; __syncthreads();
    for (int st = 128; st > 0; st >>= 1) {
        if (threadIdx.x < st) s[threadIdx.x] = fmaxf(s[threadIdx.x], s[threadIdx.x + st]);
        __syncthreads();
    }
    if (threadIdx.x == 0) g_qmax[b] = s[0];
}
__global__ void bound_M() {
    int idx = blockIdx.x*256 + threadIdx.x;
    int b = idx >> 12;
    g_M[idx] = sqrtf(g_kn2[idx] * g_qmax[b]);
}

// ---------------- stats: logits(fp16 mma) -> exp -> S[n], store E fp16 ------
__global__ void stats4() {
    extern __shared__ char smc[];
    float*  Mch = (float*)smc;                 // 128
    __half* ks  = (__half*)(smc + 512);        // 128*40
    __half* qs  = (__half*)(smc + 10752);      // 64*40
    __half* Eh  = (__half*)(smc + 15872);      // 64*EHS

    int b = blockIdx.y, n0 = blockIdx.x*128;
    int tid = threadIdx.x, w = tid >> 5, lane = tid & 31, g = lane >> 2, tig = lane & 3;

#pragma unroll
    for (int r = 0; r < 8; r++) {
        int e = r*256 + tid; int row = e >> 4, c2 = e & 15;
        float2 f = *(const float2*)(g_k + (b*NN + n0 + row)*QKD + 2*c2);
        *(__half2*)(ks + row*40 + 2*c2) = __floats2half2_rn(f.x, f.y);
    }
    if (tid < 128) Mch[tid] = g_M[b*NN + n0 + tid];
    __syncthreads();

    unsigned bb[2][2][2];
#pragma unroll
    for (int t = 0; t < 2; t++) {
        int nb = w*16 + t*8;
#pragma unroll
        for (int k2 = 0; k2 < 2; k2++) {
            const __half* p = ks + (nb + g)*40 + k2*16 + 2*tig;
            bb[t][k2][0] = LH2(p);
            bb[t][k2][1] = LH2(p + 8);
        }
    }

    float scol[4] = {0.f, 0.f, 0.f, 0.f};
    for (int m0 = 0; m0 < NN; m0 += 64) {
        __syncthreads();
#pragma unroll
        for (int r = 0; r < 4; r++) {
            int e = r*256 + tid; int row = e >> 4, c2 = e & 15;
            float2 f = *(const float2*)(g_q + (b*NN + m0 + row)*QKD + 2*c2);
            *(__half2*)(qs + row*40 + 2*c2) = __floats2half2_rn(f.x, f.y);
        }
        __syncthreads();
#pragma unroll
        for (int sw = 0; sw < 4; sw++) {
            unsigned a[2][4];
#pragma unroll
            for (int k2 = 0; k2 < 2; k2++) {
                const __half* p = qs + (sw*16 + g)*40 + k2*16 + 2*tig;
                a[k2][0] = LH2(p);
                a[k2][1] = LH2(p + 8*40);
                a[k2][2] = LH2(p + 8);
                a[k2][3] = LH2(p + 8*40 + 8);
            }
#pragma unroll
            for (int t = 0; t < 2; t++) {
                float d[4] = {0.f, 0.f, 0.f, 0.f};
#pragma unroll
                for (int k2 = 0; k2 < 2; k2++)
                    mma16(d, a[k2][0], a[k2][1], a[k2][2], a[k2][3],
                          bb[t][k2][0], bb[t][k2][1]);
                int nb = w*16 + t*8;
                float M0 = Mch[nb + 2*tig], M1 = Mch[nb + 2*tig + 1];
                float e0 = __expf(d[0] - M0), e1 = __expf(d[1] - M1);
                float e2 = __expf(d[2] - M0), e3 = __expf(d[3] - M1);
                scol[t*2]     += e0 + e2;
                scol[t*2 + 1] += e1 + e3;
                int col = nb + 2*tig;
                *(__half2*)(Eh + (sw*16 + g)*EHS     + col) = __floats2half2_rn(e0, e1);
                *(__half2*)(Eh + (sw*16 + 8 + g)*EHS + col) = __floats2half2_rn(e2, e3);
            }
        }
        __syncthreads();
#pragma unroll
        for (int r = 0; r < 4; r++) {
            int e = r*256 + tid;
            int row = e >> 4, q4 = e & 15;
            uint4 val = *(const uint4*)(Eh + row*EHS + q4*8);
            *(uint4*)(g_E + ((size_t)(b*NN + m0 + row))*NN + n0 + q4*8) = val;
        }
    }
#pragma unroll
    for (int off = 16; off >= 4; off >>= 1)
#pragma unroll
        for (int i = 0; i < 4; i++)
            scol[i] += __shfl_down_sync(0xffffffffu, scol[i], off);
    if (lane < 4) {
#pragma unroll
        for (int t = 0; t < 2; t++)
#pragma unroll
            for (int p = 0; p < 2; p++) {
                int n = w*16 + t*8 + 2*lane + p;
                g_invS[b*NN + n0 + n] = 1.f / scol[t*2 + p];
            }
    }
}

// ---------------- vprep: g_vh[b][c][n] = half(v[n][c] * invS[n]) -------------
__global__ void vprep() {
    __shared__ float s[32][33];
    int b = blockIdx.z, c0 = blockIdx.y*32, n0 = blockIdx.x*32;
    int tx = threadIdx.x, ty = threadIdx.y;
#pragma unroll
    for (int r = 0; r < 4; r++) {
        int n = n0 + ty + 8*r;
        s[ty + 8*r][tx] = g_vt[(size_t)(b*NN + n)*CC + c0 + tx] * g_invS[b*NN + n];
    }
    __syncthreads();
#pragma unroll
    for (int r = 0; r < 4; r++) {
        int c = c0 + ty + 8*r;
        g_vh[((size_t)b*CC + c)*NN + n0 + tx] = __float2half(s[tx][ty + 8*r]);
    }
}

// ---------------- attnout5: cp.async 2-stage pipeline + ldmatrix -------------
// smem per stage: E 128x40 halves (5120) + V 256x40 (10240) = 15360 halves
#define STG_H  15360
#define STG_B  30720
__global__ void __launch_bounds__(512) attnout5() {
    extern __shared__ __half smh[];
    unsigned sb = s2u(smh);

    int b = blockIdx.y, m0 = blockIdx.x*128;
    int tid = threadIdx.x, lane = tid & 31, w = tid >> 5, g = lane >> 2, tig = lane & 3;
    int mw = w & 3, cw = w >> 2;   // m = mw*32, col = cw*64

    // cp.async sources/destinations (row/c8 per thread)
    int erow = tid >> 2, ec8 = tid & 3;
    const __half* eS  = g_E  + ((size_t)(b*NN + m0 + erow))*NN + ec8*8;
    const __half* vS0 = g_vh + ((size_t)b*CC + erow)*NN + ec8*8;
    const __half* vS1 = g_vh + ((size_t)b*CC + 128 + erow)*NN + ec8*8;
    unsigned edst  = sb + (erow*40 + ec8*8)*2;
    unsigned vdst0 = sb + (5120 + erow*40 + ec8*8)*2;
    unsigned vdst1 = sb + (5120 + (128 + erow)*40 + ec8*8)*2;

    // ldmatrix base offsets (bytes, within stage)
    unsigned ab = ((mw*32 + (lane & 15))*40 + ((lane & 16) >> 1)) * 2;
    unsigned bbase = (5120 + (cw*64 + ((lane & 16) >> 1) + (lane & 7))*40
                      + ((lane & 8) ? 8 : 0)) * 2;

    float acc[2][8][4];
#pragma unroll
    for (int ms = 0; ms < 2; ms++)
#pragma unroll
        for (int i = 0; i < 8; i++)
#pragma unroll
            for (int j = 0; j < 4; j++) acc[ms][i][j] = 0.f;

    // prologue: stage 0
    CPA(edst, eS); CPA(vdst0, vS0); CPA(vdst1, vS1); CPCOMMIT();

    for (int it = 0; it < 128; it++) {
        if (it + 1 < 128) {
            int n1 = (it + 1) * 32;
            unsigned so = ((it + 1) & 1) * STG_B;
            CPA(edst + so, eS + n1);
            CPA(vdst0 + so, vS0 + n1);
            CPA(vdst1 + so, vS1 + n1);
            CPCOMMIT();
            CPWAIT1();
        } else {
            CPWAIT0();
        }
        __syncthreads();
        unsigned sbase = sb + (it & 1) * STG_B;
#pragma unroll
        for (int k2 = 0; k2 < 2; k2++) {
            unsigned a0[4], a1[4];
            LDSM4(a0[0], a0[1], a0[2], a0[3], sbase + ab + k2*32);
            LDSM4(a1[0], a1[1], a1[2], a1[3], sbase + ab + 1280 + k2*32);
#pragma unroll
            for (int pr = 0; pr < 4; pr++) {
                unsigned b0, b1, c0, c1;
                LDSM4(b0, b1, c0, c1, sbase + bbase + pr*1280 + k2*32);
                mma16(acc[0][2*pr],     a0[0], a0[1], a0[2], a0[3], b0, b1);
                mma16(acc[1][2*pr],     a1[0], a1[1], a1[2], a1[3], b0, b1);
                mma16(acc[0][2*pr + 1], a0[0], a0[1], a0[2], a0[3], c0, c1);
                mma16(acc[1][2*pr + 1], a1[0], a1[1], a1[2], a1[3], c0, c1);
            }
        }
        __syncthreads();
    }
    // epilogue: write fp16 X directly
#pragma unroll
    for (int ms = 0; ms < 2; ms++) {
        size_t row = (size_t)(b*NN + m0 + mw*32 + ms*16 + g);
#pragma unroll
        for (int t8 = 0; t8 < 8; t8++) {
            int col = cw*64 + t8*8 + 2*tig;
            *(__half2*)(g_xh + row*CC + col) =
                __floats2half2_rn(acc[ms][t8][0], acc[ms][t8][1]);
            *(__half2*)(g_xh + (row + 8)*CC + col) =
                __floats2half2_rn(acc[ms][t8][2], acc[ms][t8][3]);
        }
    }
}

// ---------------- MLP fp16: relu(X W1^T + b1) W2^T + b2 + LN partials --------
__global__ void __launch_bounds__(256, 2) mlp4(const float* __restrict__ b1,
                                               const float* __restrict__ b2) {
    extern __shared__ __half smh[];
    __half* Xs  = smh;                   // 64*264
    __half* W1s = Xs  + 64*264;          // 32*264
    __half* Hs  = W1s + 32*264;          // 64*40
    __half* W2s = Hs  + 64*40;           // 256*40

    int m0 = blockIdx.x*64;
    int tid = threadIdx.x, w = tid >> 5, lane = tid & 31, g = lane >> 2, tig = lane & 3;
    int sw = w & 3, np = w >> 2;   // GEMM1 roles
    int m2 = w & 1, c4 = w >> 1;   // GEMM2 roles

    // load whole X tile (64 x 256) fp16 directly
#pragma unroll
    for (int r = 0; r < 8; r++) {
        int e = r*256 + tid; int row = e >> 5, q = e & 31;
        *(uint4*)(Xs + row*264 + q*8) =
            *(const uint4*)(g_xh + (size_t)(m0 + row)*CC + q*8);
    }

    float acc2[2][8][4];
#pragma unroll
    for (int ms = 0; ms < 2; ms++)
#pragma unroll
        for (int i = 0; i < 8; i++)
#pragma unroll
            for (int j = 0; j < 4; j++) acc2[ms][i][j] = 0.f;

    for (int slab = 0; slab < 8; slab++) {
        __syncthreads();
#pragma unroll
        for (int r = 0; r < 16; r++) {
            int e = r*256 + tid; int row = e >> 7, c2 = e & 127;
            *(__half2*)(W1s + row*264 + 2*c2) =
                *(const __half2*)(g_W1h + (slab*32 + row)*CC + 2*c2);
        }
#pragma unroll
        for (int r = 0; r < 16; r++) {
            int e = r*256 + tid; int row = e >> 4, c2 = e & 15;
            *(__half2*)(W2s + row*40 + 2*c2) =
                *(const __half2*)(g_W2h + row*CC + slab*32 + 2*c2);
        }
        __syncthreads();
        float acc1[2][4];
#pragma unroll
        for (int t = 0; t < 2; t++)
#pragma unroll
            for (int j = 0; j < 4; j++) acc1[t][j] = 0.f;
#pragma unroll
        for (int k2 = 0; k2 < 16; k2++) {
            const __half* p = Xs + (sw*16 + g)*264 + k2*16 + 2*tig;
            unsigned a0 = LH2(p);
            unsigned a1 = LH2(p + 8*264);
            unsigned a2 = LH2(p + 8);
            unsigned a3 = LH2(p + 8*264 + 8);
#pragma unroll
            for (int t = 0; t < 2; t++) {
                const __half* bp = W1s + (np*16 + t*8 + g)*264 + k2*16 + 2*tig;
                mma16(acc1[t], a0, a1, a2, a3, LH2(bp), LH2(bp + 8));
            }
        }
#pragma unroll
        for (int t = 0; t < 2; t++) {
            int nb = np*16 + t*8;
            float bb0 = b1[slab*32 + nb + 2*tig];
            float bb1 = b1[slab*32 + nb + 2*tig + 1];
            *(__half2*)(Hs + (sw*16 + g)*40 + nb + 2*tig) =
                __floats2half2_rn(fmaxf(acc1[t][0] + bb0, 0.f), fmaxf(acc1[t][1] + bb1, 0.f));
            *(__half2*)(Hs + (sw*16 + 8 + g)*40 + nb + 2*tig) =
                __floats2half2_rn(fmaxf(acc1[t][2] + bb0, 0.f), fmaxf(acc1[t][3] + bb1, 0.f));
        }
        __syncthreads();
#pragma unroll
        for (int k2 = 0; k2 < 2; k2++) {
            unsigned a[2][4];
#pragma unroll
            for (int ms = 0; ms < 2; ms++) {
                const __half* p = Hs + (m2*32 + ms*16 + g)*40 + k2*16 + 2*tig;
                a[ms][0] = LH2(p);
                a[ms][1] = LH2(p + 8*40);
                a[ms][2] = LH2(p + 8);
                a[ms][3] = LH2(p + 8*40 + 8);
            }
#pragma unroll
            for (int t8 = 0; t8 < 8; t8++) {
                const __half* bp = W2s + (c4*64 + t8*8 + g)*40 + k2*16 + 2*tig;
                unsigned b0 = LH2(bp);
                unsigned b1 = LH2(bp + 8);
#pragma unroll
                for (int ms = 0; ms < 2; ms++)
                    mma16(acc2[ms][t8], a[ms][0], a[ms][1], a[ms][2], a[ms][3], b0, b1);
            }
        }
    }
    // epilogue + b2 + LN block partials
    float bs = 0.f, bqq = 0.f;
#pragma unroll
    for (int ms = 0; ms < 2; ms++) {
        int row = m0 + m2*32 + ms*16 + g;
#pragma unroll
        for (int t8 = 0; t8 < 8; t8++) {
            int col = c4*64 + t8*8 + 2*tig;
            float v0 = acc2[ms][t8][0] + b2[col];
            float v1 = acc2[ms][t8][1] + b2[col + 1];
            float v2 = acc2[ms][t8][2] + b2[col];
            float v3 = acc2[ms][t8][3] + b2[col + 1];
            *(float2*)(g_mlp + (size_t)row*CC + col)       = make_float2(v0, v1);
            *(float2*)(g_mlp + (size_t)(row + 8)*CC + col) = make_float2(v2, v3);
            bs  += v0 + v1 + v2 + v3;
            bqq += v0*v0 + v1*v1 + v2*v2 + v3*v3;
        }
    }
    __syncthreads();
    float* red = (float*)smh;
    red[tid] = bs; red[256 + tid] = bqq;
    __syncthreads();
    for (int st = 128; st > 0; st >>= 1) {
        if (tid < st) { red[tid] += red[tid + st]; red[256 + tid] += red[256 + tid + st]; }
        __syncthreads();
    }
    if (tid == 0) {
        g_red[blockIdx.x*2 + 0] = red[0];
        g_red[blockIdx.x*2 + 1] = red[256];
    }
}

// ---------------- LayerNorm --------------------------------------------------
__global__ void ln_final() {
    __shared__ float ss[64], sq[64];
    int b = blockIdx.x, t = threadIdx.x;
    ss[t] = g_red[(b*64 + t)*2 + 0];
    sq[t] = g_red[(b*64 + t)*2 + 1];
    __syncthreads();
    for (int st = 32; st > 0; st >>= 1) {
        if (t < st) { ss[t] += ss[t + st]; sq[t] += sq[t + st]; }
        __syncthreads();
    }
    if (t == 0) {
        const float inv = 1.0f / (float)(NN * CC);
        float mean = ss[0] * inv;
        float var  = sq[0] * inv - mean*mean;
        g_mv[b*2 + 0] = mean;
        g_mv[b*2 + 1] = rsqrtf(var + 1e-5f);
    }
}

__global__ void ln_apply(const float* __restrict__ gamma,
                         const float* __restrict__ beta,
                         float* __restrict__ out) {
    __shared__ float s[32][33];
    int b = blockIdx.z, c0 = blockIdx.y*32, n0 = blockIdx.x*32;
    int tx = threadIdx.x, ty = threadIdx.y;
    float mean = g_mv[b*2], rstd = g_mv[b*2 + 1];
#pragma unroll
    for (int r = 0; r < 4; r++) {
        int n = n0 + ty + 8*r;
        s[ty + 8*r][tx] = g_mlp[(size_t)(b*NN + n)*CC + c0 + tx];
    }
    __syncthreads();
#pragma unroll
    for (int r = 0; r < 4; r++) {
        int c = c0 + ty + 8*r;
        int n = n0 + tx;
        float v = s[tx][ty + 8*r];
        size_t gi = (size_t)c*NN + n;
        out[(size_t)b*CC*NN + gi] = (v - mean)*rstd*gamma[gi] + beta[gi];
    }
}

// ---------------- launch ----------------------------------------------------
extern "C" void kernel_launch(void* const* d_in, const int* in_sizes, int n_in,
                              void* d_out, int out_size) {
    const float* x     = (const float*)d_in[0];
    const float* Wq    = (const float*)d_in[1];
    const float* bq    = (const float*)d_in[2];
    const float* Wk    = (const float*)d_in[3];
    const float* bk    = (const float*)d_in[4];
    const float* Wv    = (const float*)d_in[5];
    const float* bv    = (const float*)d_in[6];
    const float* W1    = (const float*)d_in[7];
    const float* b1    = (const float*)d_in[8];
    const float* W2    = (const float*)d_in[9];
    const float* b2    = (const float*)d_in[10];
    const float* gamma = (const float*)d_in[11];
    const float* beta  = (const float*)d_in[12];
    float* out = (float*)d_out;

    const int stats_smem = 512 + (128*40 + 64*40 + 64*EHS)*2;     // 33280
    const int attn_smem  = 2*STG_B;                               // 61440
    const int mlp_smem   = (64*264 + 32*264 + 64*40 + 256*40)*2;  // 76288
    cudaFuncSetAttribute(stats4,   cudaFuncAttributeMaxDynamicSharedMemorySize, stats_smem);
    cudaFuncSetAttribute(attnout5, cudaFuncAttributeMaxDynamicSharedMemorySize, attn_smem);
    cudaFuncSetAttribute(mlp4,     cudaFuncAttributeMaxDynamicSharedMemorySize, mlp_smem);

    wprep<<<(2*CC*CC)/256, 256>>>(W1, W2);
    qkv_mma<<<dim3(NN/64, 5, BB), 256>>>(x, Wq, bq, Wk, bk, Wv, bv);
    bound_norms<<<(BB*NN)/256, 256>>>();
    bound_qmax<<<BB, 256>>>();
    bound_M<<<(BB*NN)/256, 256>>>();
    stats4<<<dim3(NN/128, BB), 256, stats_smem>>>();
    vprep<<<dim3(NN/32, CC/32, BB), dim3(32, 8)>>>();
    attnout5<<<dim3(NN/128, BB), 512, attn_smem>>>();
    mlp4<<<(BB*NN)/64, 256, mlp_smem>>>(b1, b2);
    ln_final<<<BB, 64>>>();
    ln_apply<<<dim3(NN/32, CC/32, BB), dim3(32, 8)>>>(gamma, beta, out);
}

// round 13
// speedup vs baseline: 5.3802x; 1.0658x over previous
#include <cuda_runtime.h>
#include <cuda_fp16.h>
#include <math.h>

#define BB   8
#define CC   256
#define NN   4096
#define QKD  32
#define SCALE 0.17677669529663687f  /* 32^-0.5 */
#define EHS  136

// ---------------- scratch ---------------------------------------------------
__device__ __align__(16) __half g_qh[BB*NN*QKD];   // fp16 q (scaled, +bq)
__device__ __align__(16) __half g_kh[BB*NN*QKD];   // fp16 k (+bk)
__device__ float  g_vt[BB*NN*CC];                  // [b][n][c] (+bv)
__device__ float  g_invS[BB*NN];
__device__ __align__(16) __half g_E[(size_t)BB*NN*NN];   // E[b][m][n] fp16
__device__ __align__(16) __half g_vh[(size_t)BB*CC*NN];  // [b][c][n] fp16, *invS
__device__ __align__(16) __half g_xh[(size_t)BB*NN*CC];  // attention out fp16 [m][c]
__device__ float  g_mlp[BB*NN*CC];
__device__ __half g_W1h[CC*CC];              // [o][c] fp16
__device__ __half g_W2h[CC*CC];
__device__ float  g_kn2[BB*NN];
__device__ float  g_qmax[BB];
__device__ float  g_red[BB*64*2];
__device__ float  g_mv[BB*2];

// ---------------- helpers ----------------------------------------------------
__device__ __forceinline__ float tf32r(float x) {
    unsigned u;
    asm("cvt.rna.tf32.f32 %0, %1;" : "=r"(u) : "f"(x));
    return __uint_as_float(u);
}
__device__ __forceinline__ void mma8(float* c,
                                     unsigned a0, unsigned a1, unsigned a2, unsigned a3,
                                     unsigned b0, unsigned b1) {
    asm volatile("mma.sync.aligned.m16n8k8.row.col.f32.tf32.tf32.f32 "
                 "{%0,%1,%2,%3}, {%4,%5,%6,%7}, {%8,%9}, {%0,%1,%2,%3};\n"
                 : "+f"(c[0]), "+f"(c[1]), "+f"(c[2]), "+f"(c[3])
                 : "r"(a0), "r"(a1), "r"(a2), "r"(a3), "r"(b0), "r"(b1));
}
__device__ __forceinline__ void mma16(float* c,
                                      unsigned a0, unsigned a1, unsigned a2, unsigned a3,
                                      unsigned b0, unsigned b1) {
    asm volatile("mma.sync.aligned.m16n8k16.row.col.f32.f16.f16.f32 "
                 "{%0,%1,%2,%3}, {%4,%5,%6,%7}, {%8,%9}, {%0,%1,%2,%3};\n"
                 : "+f"(c[0]), "+f"(c[1]), "+f"(c[2]), "+f"(c[3])
                 : "r"(a0), "r"(a1), "r"(a2), "r"(a3), "r"(b0), "r"(b1));
}
#define FU  __float_as_uint
#define LH2(p) (*(const unsigned*)(p))
#define CPA(dst, src)  asm volatile("cp.async.cg.shared.global [%0], [%1], 16;\n" :: "r"(dst), "l"(src))
#define CPCOMMIT()     asm volatile("cp.async.commit_group;\n")
#define CPWAIT1()      asm volatile("cp.async.wait_group 1;\n" ::: "memory")
#define CPWAIT0()      asm volatile("cp.async.wait_group 0;\n" ::: "memory")
#define LDSM4(r0,r1,r2,r3,addr) \
    asm volatile("ldmatrix.sync.aligned.m8n8.x4.shared.b16 {%0,%1,%2,%3}, [%4];" \
                 : "=r"(r0), "=r"(r1), "=r"(r2), "=r"(r3) : "r"(addr))

__device__ __forceinline__ unsigned s2u(const void* p) {
    unsigned a;
    asm("{ .reg .u64 t; cvta.to.shared.u64 t, %1; cvt.u32.u64 %0, t; }" : "=r"(a) : "l"(p));
    return a;
}

// ---------------- weight prep + qmax zero ------------------------------------
__global__ void wprep(const float* __restrict__ W1, const float* __restrict__ W2) {
    int i = blockIdx.x*256 + threadIdx.x;
    if (i < 8) g_qmax[i] = 0.f;
    if (i < CC*CC) g_W1h[i] = __float2half(W1[i]);
    else           g_W2h[i - CC*CC] = __float2half(W2[i - CC*CC]);
}

// ---------------- q/k/v projection via tf32 mma ------------------------------
#define XS 72
__global__ void qkv_mma(const float* __restrict__ x,
                        const float* __restrict__ Wq, const float* __restrict__ bq,
                        const float* __restrict__ Wk, const float* __restrict__ bk,
                        const float* __restrict__ Wv, const float* __restrict__ bv) {
    __shared__ float xs[32*XS];
    __shared__ float ws[64*40];
    int b  = blockIdx.z;
    int o0 = blockIdx.y * 64;
    int n0 = blockIdx.x * 64;
    int tid = threadIdx.x, w = tid >> 5, lane = tid & 31, g = lane >> 2, tig = lane & 3;
    int sw = w & 3, np = w >> 2;
    const float* xb = x + (size_t)b * CC * NN;

    float acc[4][4];
#pragma unroll
    for (int i = 0; i < 4; i++)
#pragma unroll
        for (int j = 0; j < 4; j++) acc[i][j] = 0.f;

    for (int c0 = 0; c0 < CC; c0 += 32) {
        __syncthreads();
#pragma unroll
        for (int r = 0; r < 8; r++) {
            int e = r*256 + tid; int cc = e >> 6, nn = e & 63;
            xs[cc*XS + nn] = tf32r(xb[(c0 + cc)*NN + n0 + nn]);
        }
#pragma unroll
        for (int r = 0; r < 8; r++) {
            int e = r*256 + tid; int oo = e >> 5, cc = e & 31;
            int o = o0 + oo;
            const float* Wr = (o < 32) ? (Wq + o*CC)
                            : (o < 64) ? (Wk + (o-32)*CC)
                                       : (Wv + (o-64)*CC);
            ws[oo*40 + cc] = tf32r(Wr[c0 + cc]);
        }
        __syncthreads();
#pragma unroll
        for (int k4 = 0; k4 < 4; k4++) {
            int k0 = k4*8;
            unsigned a0 = FU(xs[(k0 + tig)*XS     + sw*16 + g]);
            unsigned a1 = FU(xs[(k0 + tig)*XS     + sw*16 + 8 + g]);
            unsigned a2 = FU(xs[(k0 + tig + 4)*XS + sw*16 + g]);
            unsigned a3 = FU(xs[(k0 + tig + 4)*XS + sw*16 + 8 + g]);
#pragma unroll
            for (int t8 = 0; t8 < 4; t8++) {
                int oc = np*32 + t8*8 + g;
                unsigned b0 = FU(ws[oc*40 + k0 + tig]);
                unsigned b1 = FU(ws[oc*40 + k0 + tig + 4]);
                mma8(acc[t8], a0, a1, a2, a3, b0, b1);
            }
        }
    }
#pragma unroll
    for (int t8 = 0; t8 < 4; t8++) {
#pragma unroll
        for (int rr = 0; rr < 2; rr++) {
            int n = n0 + sw*16 + g + rr*8;
            int o = o0 + np*32 + t8*8 + 2*tig;
            float v0 = acc[t8][rr*2 + 0];
            float v1 = acc[t8][rr*2 + 1];
            if (o < 32) {
                *(__half2*)(g_qh + (b*NN + n)*QKD + o) =
                    __floats2half2_rn((v0 + __ldg(bq + o)) * SCALE,
                                      (v1 + __ldg(bq + o + 1)) * SCALE);
            } else if (o < 64) {
                *(__half2*)(g_kh + (b*NN + n)*QKD + (o - 32)) =
                    __floats2half2_rn(v0 + __ldg(bk + o - 32),
                                      v1 + __ldg(bk + o - 31));
            } else {
                g_vt[(size_t)(b*NN + n)*CC + (o - 64)] = v0 + __ldg(bv + o - 64);
                g_vt[(size_t)(b*NN + n)*CC + (o - 63)] = v1 + __ldg(bv + o - 63);
            }
        }
    }
}

// ---------------- norms: kn2 + block-max qn2 -> atomicMax qmax ---------------
__global__ void bound_norms() {
    __shared__ float s[256];
    int idx = blockIdx.x*256 + threadIdx.x;
    int b = idx >> 12;
    const __half* qp = g_qh + idx*QKD;
    const __half* kp = g_kh + idx*QKD;
    float qs = 0.f, ks = 0.f;
#pragma unroll
    for (int j = 0; j < QKD/2; j++) {
        float2 q2 = __half22float2(*(const __half2*)(qp + 2*j));
        float2 k2 = __half22float2(*(const __half2*)(kp + 2*j));
        qs = fmaf(q2.x, q2.x, qs); qs = fmaf(q2.y, q2.y, qs);
        ks = fmaf(k2.x, k2.x, ks); ks = fmaf(k2.y, k2.y, ks);
    }
    g_kn2[idx] = ks;
    s[threadIdx.x] = qs; __syncthreads();
    for (int st = 128; st > 0; st >>= 1) {
        if (threadIdx.x < st) s[threadIdx.x] = fmaxf(s[threadIdx.x], s[threadIdx.x + st]);
        __syncthreads();
    }
    if (threadIdx.x == 0)
        atomicMax((int*)&g_qmax[b], __float_as_int(s[0]));
}

// ---------------- stats5: pipelined logits(mma) -> exp -> S[n], E fp16 -------
// smem: Mch 512B | ks 10240B | qs0 5120B | qs1 5120B | Eh 17408B = 38400B
__global__ void stats5() {
    extern __shared__ char smc[];
    float*  Mch = (float*)smc;
    __half* ks  = (__half*)(smc + 512);
    __half* Eh  = (__half*)(smc + 20992);
    unsigned sb = s2u(smc);

    int b = blockIdx.y, n0 = blockIdx.x*128;
    int tid = threadIdx.x, w = tid >> 5, lane = tid & 31, g = lane >> 2, tig = lane & 3;

    // k tile: 128 rows x 32 halves = 512 uint4 (4 per row)
#pragma unroll
    for (int r = 0; r < 2; r++) {
        int e = r*256 + tid; int row = e >> 2, part = e & 3;
        *(uint4*)(ks + row*40 + part*8) =
            *(const uint4*)(g_kh + (b*NN + n0 + row)*QKD + part*8);
    }
    if (tid < 128)
        Mch[tid] = sqrtf(g_kn2[b*NN + n0 + tid] * g_qmax[b]);
    __syncthreads();

    // hoist B fragments (this warp's 16 n-cols)
    unsigned bb[2][2][2];
#pragma unroll
    for (int t = 0; t < 2; t++) {
        int nb = w*16 + t*8;
#pragma unroll
        for (int k2 = 0; k2 < 2; k2++) {
            const __half* p = ks + (nb + g)*40 + k2*16 + 2*tig;
            bb[t][k2][0] = LH2(p);
            bb[t][k2][1] = LH2(p + 8);
        }
    }

    // cp.async q pipeline
    int qrow = tid >> 2, qc8 = (tid & 3)*8;
    const __half* qsrc = g_qh + ((size_t)(b*NN) + qrow)*QKD + qc8;
    unsigned qdst = sb + 10752 + (qrow*40 + qc8)*2;
    unsigned abase = sb + 10752 + ((lane & 15)*40 + ((lane & 16) >> 1))*2;
    CPA(qdst, qsrc); CPCOMMIT();

    float scol[4] = {0.f, 0.f, 0.f, 0.f};
    for (int it = 0; it < 64; it++) {
        if (it + 1 < 64) {
            CPA(qdst + ((it + 1) & 1)*5120, qsrc + (it + 1)*64*QKD);
            CPCOMMIT();
            CPWAIT1();
        } else {
            CPWAIT0();
        }
        __syncthreads();
        unsigned qb = abase + (it & 1)*5120;
#pragma unroll
        for (int sw = 0; sw < 4; sw++) {
            unsigned a[2][4];
            LDSM4(a[0][0], a[0][1], a[0][2], a[0][3], qb + sw*1280);
            LDSM4(a[1][0], a[1][1], a[1][2], a[1][3], qb + sw*1280 + 32);
#pragma unroll
            for (int t = 0; t < 2; t++) {
                float d[4] = {0.f, 0.f, 0.f, 0.f};
#pragma unroll
                for (int k2 = 0; k2 < 2; k2++)
                    mma16(d, a[k2][0], a[k2][1], a[k2][2], a[k2][3],
                          bb[t][k2][0], bb[t][k2][1]);
                int nb = w*16 + t*8;
                float M0 = Mch[nb + 2*tig], M1 = Mch[nb + 2*tig + 1];
                float e0 = __expf(d[0] - M0), e1 = __expf(d[1] - M1);
                float e2 = __expf(d[2] - M0), e3 = __expf(d[3] - M1);
                scol[t*2]     += e0 + e2;
                scol[t*2 + 1] += e1 + e3;
                int col = nb + 2*tig;
                *(__half2*)(Eh + (sw*16 + g)*EHS     + col) = __floats2half2_rn(e0, e1);
                *(__half2*)(Eh + (sw*16 + 8 + g)*EHS + col) = __floats2half2_rn(e2, e3);
            }
        }
        __syncthreads();
#pragma unroll
        for (int r = 0; r < 4; r++) {
            int e = r*256 + tid;
            int row = e >> 4, q4 = e & 15;
            uint4 val = *(const uint4*)(Eh + row*EHS + q4*8);
            *(uint4*)(g_E + ((size_t)(b*NN + it*64 + row))*NN + n0 + q4*8) = val;
        }
    }
#pragma unroll
    for (int off = 16; off >= 4; off >>= 1)
#pragma unroll
        for (int i = 0; i < 4; i++)
            scol[i] += __shfl_down_sync(0xffffffffu, scol[i], off);
    if (lane < 4) {
#pragma unroll
        for (int t = 0; t < 2; t++)
#pragma unroll
            for (int p = 0; p < 2; p++) {
                int n = w*16 + t*8 + 2*lane + p;
                g_invS[b*NN + n0 + n] = 1.f / scol[t*2 + p];
            }
    }
}

// ---------------- vprep: g_vh[b][c][n] = half(v[n][c] * invS[n]) -------------
__global__ void vprep() {
    __shared__ float s[32][33];
    int b = blockIdx.z, c0 = blockIdx.y*32, n0 = blockIdx.x*32;
    int tx = threadIdx.x, ty = threadIdx.y;
#pragma unroll
    for (int r = 0; r < 4; r++) {
        int n = n0 + ty + 8*r;
        s[ty + 8*r][tx] = g_vt[(size_t)(b*NN + n)*CC + c0 + tx] * g_invS[b*NN + n];
    }
    __syncthreads();
#pragma unroll
    for (int r = 0; r < 4; r++) {
        int c = c0 + ty + 8*r;
        g_vh[((size_t)b*CC + c)*NN + n0 + tx] = __float2half(s[tx][ty + 8*r]);
    }
}

// ---------------- attnout5: cp.async 2-stage pipeline + ldmatrix -------------
#define STG_H  15360
#define STG_B  30720
__global__ void __launch_bounds__(512) attnout5() {
    extern __shared__ __half smh[];
    unsigned sb = s2u(smh);

    int b = blockIdx.y, m0 = blockIdx.x*128;
    int tid = threadIdx.x, lane = tid & 31, w = tid >> 5, g = lane >> 2, tig = lane & 3;
    int mw = w & 3, cw = w >> 2;

    int erow = tid >> 2, ec8 = tid & 3;
    const __half* eS  = g_E  + ((size_t)(b*NN + m0 + erow))*NN + ec8*8;
    const __half* vS0 = g_vh + ((size_t)b*CC + erow)*NN + ec8*8;
    const __half* vS1 = g_vh + ((size_t)b*CC + 128 + erow)*NN + ec8*8;
    unsigned edst  = sb + (erow*40 + ec8*8)*2;
    unsigned vdst0 = sb + (5120 + erow*40 + ec8*8)*2;
    unsigned vdst1 = sb + (5120 + (128 + erow)*40 + ec8*8)*2;

    unsigned ab = ((mw*32 + (lane & 15))*40 + ((lane & 16) >> 1)) * 2;
    unsigned bbase = (5120 + (cw*64 + ((lane & 16) >> 1) + (lane & 7))*40
                      + ((lane & 8) ? 8 : 0)) * 2;

    float acc[2][8][4];
#pragma unroll
    for (int ms = 0; ms < 2; ms++)
#pragma unroll
        for (int i = 0; i < 8; i++)
#pragma unroll
            for (int j = 0; j < 4; j++) acc[ms][i][j] = 0.f;

    CPA(edst, eS); CPA(vdst0, vS0); CPA(vdst1, vS1); CPCOMMIT();

    for (int it = 0; it < 128; it++) {
        if (it + 1 < 128) {
            int n1 = (it + 1) * 32;
            unsigned so = ((it + 1) & 1) * STG_B;
            CPA(edst + so, eS + n1);
            CPA(vdst0 + so, vS0 + n1);
            CPA(vdst1 + so, vS1 + n1);
            CPCOMMIT();
            CPWAIT1();
        } else {
            CPWAIT0();
        }
        __syncthreads();
        unsigned sbase = sb + (it & 1) * STG_B;
#pragma unroll
        for (int k2 = 0; k2 < 2; k2++) {
            unsigned a0[4], a1[4];
            LDSM4(a0[0], a0[1], a0[2], a0[3], sbase + ab + k2*32);
            LDSM4(a1[0], a1[1], a1[2], a1[3], sbase + ab + 1280 + k2*32);
#pragma unroll
            for (int pr = 0; pr < 4; pr++) {
                unsigned b0, b1, c0, c1;
                LDSM4(b0, b1, c0, c1, sbase + bbase + pr*1280 + k2*32);
                mma16(acc[0][2*pr],     a0[0], a0[1], a0[2], a0[3], b0, b1);
                mma16(acc[1][2*pr],     a1[0], a1[1], a1[2], a1[3], b0, b1);
                mma16(acc[0][2*pr + 1], a0[0], a0[1], a0[2], a0[3], c0, c1);
                mma16(acc[1][2*pr + 1], a1[0], a1[1], a1[2], a1[3], c0, c1);
            }
        }
        __syncthreads();
    }
#pragma unroll
    for (int ms = 0; ms < 2; ms++) {
        size_t row = (size_t)(b*NN + m0 + mw*32 + ms*16 + g);
#pragma unroll
        for (int t8 = 0; t8 < 8; t8++) {
            int col = cw*64 + t8*8 + 2*tig;
            *(__half2*)(g_xh + row*CC + col) =
                __floats2half2_rn(acc[ms][t8][0], acc[ms][t8][1]);
            *(__half2*)(g_xh + (row + 8)*CC + col) =
                __floats2half2_rn(acc[ms][t8][2], acc[ms][t8][3]);
        }
    }
}

// ---------------- MLP fp16 (ldmatrix) + LN partials --------------------------
__global__ void __launch_bounds__(256, 2) mlp5(const float* __restrict__ b1,
                                               const float* __restrict__ b2) {
    extern __shared__ __half smh[];
    __half* Xs  = smh;                   // 64*264
    __half* W1s = Xs  + 64*264;          // 32*264
    __half* Hs  = W1s + 32*264;          // 64*40
    __half* W2s = Hs  + 64*40;           // 256*40

    int m0 = blockIdx.x*64;
    int tid = threadIdx.x, w = tid >> 5, lane = tid & 31, g = lane >> 2, tig = lane & 3;
    int sw = w & 3, np = w >> 2;   // GEMM1 roles
    int m2 = w & 1, c4 = w >> 1;   // GEMM2 roles

    unsigned aadr1 = s2u(Xs)  + ((sw*16 + (lane & 15))*264 + ((lane & 16) >> 1))*2;
    unsigned badr1 = s2u(W1s) + ((np*16 + ((lane & 16) >> 1) + (lane & 7))*264
                                 + ((lane & 8) ? 8 : 0))*2;
    unsigned hadr  = s2u(Hs)  + ((m2*32 + (lane & 15))*40 + ((lane & 16) >> 1))*2;
    unsigned w2adr = s2u(W2s) + ((c4*64 + ((lane & 16) >> 1) + (lane & 7))*40
                                 + ((lane & 8) ? 8 : 0))*2;

    // load whole X tile (64 x 256) fp16
#pragma unroll
    for (int r = 0; r < 8; r++) {
        int e = r*256 + tid; int row = e >> 5, q = e & 31;
        *(uint4*)(Xs + row*264 + q*8) =
            *(const uint4*)(g_xh + (size_t)(m0 + row)*CC + q*8);
    }

    float acc2[2][8][4];
#pragma unroll
    for (int ms = 0; ms < 2; ms++)
#pragma unroll
        for (int i = 0; i < 8; i++)
#pragma unroll
            for (int j = 0; j < 4; j++) acc2[ms][i][j] = 0.f;

    for (int slab = 0; slab < 8; slab++) {
        __syncthreads();
#pragma unroll
        for (int r = 0; r < 16; r++) {
            int e = r*256 + tid; int row = e >> 7, c2 = e & 127;
            *(__half2*)(W1s + row*264 + 2*c2) =
                *(const __half2*)(g_W1h + (slab*32 + row)*CC + 2*c2);
        }
#pragma unroll
        for (int r = 0; r < 16; r++) {
            int e = r*256 + tid; int row = e >> 4, c2 = e & 15;
            *(__half2*)(W2s + row*40 + 2*c2) =
                *(const __half2*)(g_W2h + row*CC + slab*32 + 2*c2);
        }
        __syncthreads();
        // GEMM1: H_slab[64 x 32] = X @ W1_slab^T  (ldmatrix)
        float acc1[2][4];
#pragma unroll
        for (int t = 0; t < 2; t++)
#pragma unroll
            for (int j = 0; j < 4; j++) acc1[t][j] = 0.f;
#pragma unroll
        for (int k2 = 0; k2 < 16; k2++) {
            unsigned a0, a1, a2, a3, b0, b1, c0, c1;
            LDSM4(a0, a1, a2, a3, aadr1 + k2*32);
            LDSM4(b0, b1, c0, c1, badr1 + k2*32);
            mma16(acc1[0], a0, a1, a2, a3, b0, b1);
            mma16(acc1[1], a0, a1, a2, a3, c0, c1);
        }
#pragma unroll
        for (int t = 0; t < 2; t++) {
            int nb = np*16 + t*8;
            float bb0 = b1[slab*32 + nb + 2*tig];
            float bb1 = b1[slab*32 + nb + 2*tig + 1];
            *(__half2*)(Hs + (sw*16 + g)*40 + nb + 2*tig) =
                __floats2half2_rn(fmaxf(acc1[t][0] + bb0, 0.f), fmaxf(acc1[t][1] + bb1, 0.f));
            *(__half2*)(Hs + (sw*16 + 8 + g)*40 + nb + 2*tig) =
                __floats2half2_rn(fmaxf(acc1[t][2] + bb0, 0.f), fmaxf(acc1[t][3] + bb1, 0.f));
        }
        __syncthreads();
        // GEMM2 partial: acc2 += H_slab @ W2_slab^T  (ldmatrix)
#pragma unroll
        for (int k2 = 0; k2 < 2; k2++) {
            unsigned a0[4], a1[4];
            LDSM4(a0[0], a0[1], a0[2], a0[3], hadr + k2*32);
            LDSM4(a1[0], a1[1], a1[2], a1[3], hadr + 1280 + k2*32);
#pragma unroll
            for (int pr = 0; pr < 4; pr++) {
                unsigned b0, b1, c0, c1;
                LDSM4(b0, b1, c0, c1, w2adr + pr*1280 + k2*32);
                mma16(acc2[0][2*pr],     a0[0], a0[1], a0[2], a0[3], b0, b1);
                mma16(acc2[1][2*pr],     a1[0], a1[1], a1[2], a1[3], b0, b1);
                mma16(acc2[0][2*pr + 1], a0[0], a0[1], a0[2], a0[3], c0, c1);
                mma16(acc2[1][2*pr + 1], a1[0], a1[1], a1[2], a1[3], c0, c1);
            }
        }
    }
    // epilogue + b2 + LN block partials
    float bs = 0.f, bqq = 0.f;
#pragma unroll
    for (int ms = 0; ms < 2; ms++) {
        int row = m0 + m2*32 + ms*16 + g;
#pragma unroll
        for (int t8 = 0; t8 < 8; t8++) {
            int col = c4*64 + t8*8 + 2*tig;
            float v0 = acc2[ms][t8][0] + b2[col];
            float v1 = acc2[ms][t8][1] + b2[col + 1];
            float v2 = acc2[ms][t8][2] + b2[col];
            float v3 = acc2[ms][t8][3] + b2[col + 1];
            *(float2*)(g_mlp + (size_t)row*CC + col)       = make_float2(v0, v1);
            *(float2*)(g_mlp + (size_t)(row + 8)*CC + col) = make_float2(v2, v3);
            bs  += v0 + v1 + v2 + v3;
            bqq += v0*v0 + v1*v1 + v2*v2 + v3*v3;
        }
    }
    __syncthreads();
    float* red = (float*)smh;
    red[tid] = bs; red[256 + tid] = bqq;
    __syncthreads();
    for (int st = 128; st > 0; st >>= 1) {
        if (tid < st) { red[tid] += red[tid + st]; red[256 + tid] += red[256 + tid + st]; }
        __syncthreads();
    }
    if (tid == 0) {
        g_red[blockIdx.x*2 + 0] = red[0];
        g_red[blockIdx.x*2 + 1] = red[256];
    }
}

// ---------------- LayerNorm --------------------------------------------------
__global__ void ln_final() {
    __shared__ float ss[64], sq[64];
    int b = blockIdx.x, t = threadIdx.x;
    ss[t] = g_red[(b*64 + t)*2 + 0];
    sq[t] = g_red[(b*64 + t)*2 + 1];
    __syncthreads();
    for (int st = 32; st > 0; st >>= 1) {
        if (t < st) { ss[t] += ss[t + st]; sq[t] += sq[t + st]; }
        __syncthreads();
    }
    if (t == 0) {
        const float inv = 1.0f / (float)(NN * CC);
        float mean = ss[0] * inv;
        float var  = sq[0] * inv - mean*mean;
        g_mv[b*2 + 0] = mean;
        g_mv[b*2 + 1] = rsqrtf(var + 1e-5f);
    }
}

__global__ void ln_apply(const float* __restrict__ gamma,
                         const float* __restrict__ beta,
                         float* __restrict__ out) {
    __shared__ float s[32][33];
    int b = blockIdx.z, c0 = blockIdx.y*32, n0 = blockIdx.x*32;
    int tx = threadIdx.x, ty = threadIdx.y;
    float mean = g_mv[b*2], rstd = g_mv[b*2 + 1];
#pragma unroll
    for (int r = 0; r < 4; r++) {
        int n = n0 + ty + 8*r;
        s[ty + 8*r][tx] = g_mlp[(size_t)(b*NN + n)*CC + c0 + tx];
    }
    __syncthreads();
#pragma unroll
    for (int r = 0; r < 4; r++) {
        int c = c0 + ty + 8*r;
        int n = n0 + tx;
        float v = s[tx][ty + 8*r];
        size_t gi = (size_t)c*NN + n;
        out[(size_t)b*CC*NN + gi] = (v - mean)*rstd*gamma[gi] + beta[gi];
    }
}

// ---------------- launch ----------------------------------------------------
extern "C" void kernel_launch(void* const* d_in, const int* in_sizes, int n_in,
                              void* d_out, int out_size) {
    const float* x     = (const float*)d_in[0];
    const float* Wq    = (const float*)d_in[1];
    const float* bq    = (const float*)d_in[2];
    const float* Wk    = (const float*)d_in[3];
    const float* bk    = (const float*)d_in[4];
    const float* Wv    = (const float*)d_in[5];
    const float* bv    = (const float*)d_in[6];
    const float* W1    = (const float*)d_in[7];
    const float* b1    = (const float*)d_in[8];
    const float* W2    = (const float*)d_in[9];
    const float* b2    = (const float*)d_in[10];
    const float* gamma = (const float*)d_in[11];
    const float* beta  = (const float*)d_in[12];
    float* out = (float*)d_out;

    const int stats_smem = 38400;
    const int attn_smem  = 2*STG_B;                               // 61440
    const int mlp_smem   = (64*264 + 32*264 + 64*40 + 256*40)*2;  // 76288
    cudaFuncSetAttribute(stats5,   cudaFuncAttributeMaxDynamicSharedMemorySize, stats_smem);
    cudaFuncSetAttribute(attnout5, cudaFuncAttributeMaxDynamicSharedMemorySize, attn_smem);
    cudaFuncSetAttribute(mlp5,     cudaFuncAttributeMaxDynamicSharedMemorySize, mlp_smem);

    wprep<<<(2*CC*CC)/256, 256>>>(W1, W2);
    qkv_mma<<<dim3(NN/64, 5, BB), 256>>>(x, Wq, bq, Wk, bk, Wv, bv);
    bound_norms<<<(BB*NN)/256, 256>>>();
    stats5<<<dim3(NN/128, BB), 256, stats_smem>>>();
    vprep<<<dim3(NN/32, CC/32, BB), dim3(32, 8)>>>();
    attnout5<<<dim3(NN/128, BB), 512, attn_smem>>>();
    mlp5<<<(BB*NN)/64, 256, mlp_smem>>>(b1, b2);
    ln_final<<<BB, 64>>>();
    ln_apply<<<dim3(NN/32, CC/32, BB), dim3(32, 8)>>>(gamma, beta, out);
}

// round 14
// speedup vs baseline: 5.7501x; 1.0688x over previous
#include <cuda_runtime.h>
#include <cuda_fp16.h>
#include <math.h>

#define BB   8
#define CC   256
#define NN   4096
#define QKD  32
#define SCALE 0.17677669529663687f  /* 32^-0.5 */
#define L2E   1.44269504088896f
#define EHS  136

// ---------------- scratch ---------------------------------------------------
__device__ __align__(16) __half g_qh[BB*NN*QKD];   // fp16 q (scaled, +bq)
__device__ __align__(16) __half g_kh[BB*NN*QKD];   // fp16 k (+bk)
__device__ __align__(16) __half g_vth[BB*NN*CC];   // fp16 v [n][c] (+bv, unscaled)
__device__ float  g_invS[BB*NN];
__device__ __align__(16) __half g_E[(size_t)BB*NN*NN];   // E[b][m][n] fp16
__device__ __align__(16) __half g_vh[(size_t)BB*CC*NN];  // [b][c][n] fp16, *invS
__device__ __align__(16) __half g_xh[(size_t)BB*NN*CC];  // attention out fp16 [m][c]
__device__ __align__(16) __half g_mlph[(size_t)BB*NN*CC];// mlp out fp16 [m][c]
__device__ __half g_W1h[CC*CC];              // [o][c] fp16
__device__ __half g_W2h[CC*CC];
__device__ float  g_kn2[BB*NN];
__device__ float  g_qmax[BB];
__device__ float  g_red[BB*64*2];
__device__ float  g_mv[BB*2];

// ---------------- helpers ----------------------------------------------------
__device__ __forceinline__ float tf32r(float x) {
    unsigned u;
    asm("cvt.rna.tf32.f32 %0, %1;" : "=r"(u) : "f"(x));
    return __uint_as_float(u);
}
__device__ __forceinline__ float fex2(float x) {
    float r;
    asm("ex2.approx.f32 %0, %1;" : "=f"(r) : "f"(x));
    return r;
}
__device__ __forceinline__ void mma8(float* c,
                                     unsigned a0, unsigned a1, unsigned a2, unsigned a3,
                                     unsigned b0, unsigned b1) {
    asm volatile("mma.sync.aligned.m16n8k8.row.col.f32.tf32.tf32.f32 "
                 "{%0,%1,%2,%3}, {%4,%5,%6,%7}, {%8,%9}, {%0,%1,%2,%3};\n"
                 : "+f"(c[0]), "+f"(c[1]), "+f"(c[2]), "+f"(c[3])
                 : "r"(a0), "r"(a1), "r"(a2), "r"(a3), "r"(b0), "r"(b1));
}
__device__ __forceinline__ void mma16(float* c,
                                      unsigned a0, unsigned a1, unsigned a2, unsigned a3,
                                      unsigned b0, unsigned b1) {
    asm volatile("mma.sync.aligned.m16n8k16.row.col.f32.f16.f16.f32 "
                 "{%0,%1,%2,%3}, {%4,%5,%6,%7}, {%8,%9}, {%0,%1,%2,%3};\n"
                 : "+f"(c[0]), "+f"(c[1]), "+f"(c[2]), "+f"(c[3])
                 : "r"(a0), "r"(a1), "r"(a2), "r"(a3), "r"(b0), "r"(b1));
}
#define FU  __float_as_uint
#define LH2(p) (*(const unsigned*)(p))
#define CPA(dst, src)  asm volatile("cp.async.cg.shared.global [%0], [%1], 16;\n" :: "r"(dst), "l"(src))
#define CPCOMMIT()     asm volatile("cp.async.commit_group;\n")
#define CPWAIT1()      asm volatile("cp.async.wait_group 1;\n" ::: "memory")
#define CPWAIT0()      asm volatile("cp.async.wait_group 0;\n" ::: "memory")
#define LDSM4(r0,r1,r2,r3,addr) \
    asm volatile("ldmatrix.sync.aligned.m8n8.x4.shared.b16 {%0,%1,%2,%3}, [%4];" \
                 : "=r"(r0), "=r"(r1), "=r"(r2), "=r"(r3) : "r"(addr))

__device__ __forceinline__ unsigned s2u(const void* p) {
    unsigned a;
    asm("{ .reg .u64 t; cvta.to.shared.u64 t, %1; cvt.u32.u64 %0, t; }" : "=r"(a) : "l"(p));
    return a;
}

// ---------------- weight prep + qmax zero ------------------------------------
__global__ void wprep(const float* __restrict__ W1, const float* __restrict__ W2) {
    int i = blockIdx.x*256 + threadIdx.x;
    if (i < 8) g_qmax[i] = 0.f;
    if (i < CC*CC) g_W1h[i] = __float2half(W1[i]);
    else           g_W2h[i - CC*CC] = __float2half(W2[i - CC*CC]);
}

// ---------------- q/k/v projection via tf32 mma ------------------------------
#define XS 72
__global__ void qkv_mma(const float* __restrict__ x,
                        const float* __restrict__ Wq, const float* __restrict__ bq,
                        const float* __restrict__ Wk, const float* __restrict__ bk,
                        const float* __restrict__ Wv, const float* __restrict__ bv) {
    __shared__ float xs[32*XS];
    __shared__ float ws[64*40];
    int b  = blockIdx.z;
    int o0 = blockIdx.y * 64;
    int n0 = blockIdx.x * 64;
    int tid = threadIdx.x, w = tid >> 5, lane = tid & 31, g = lane >> 2, tig = lane & 3;
    int sw = w & 3, np = w >> 2;
    const float* xb = x + (size_t)b * CC * NN;

    float acc[4][4];
#pragma unroll
    for (int i = 0; i < 4; i++)
#pragma unroll
        for (int j = 0; j < 4; j++) acc[i][j] = 0.f;

    for (int c0 = 0; c0 < CC; c0 += 32) {
        __syncthreads();
#pragma unroll
        for (int r = 0; r < 8; r++) {
            int e = r*256 + tid; int cc = e >> 6, nn = e & 63;
            xs[cc*XS + nn] = tf32r(xb[(c0 + cc)*NN + n0 + nn]);
        }
#pragma unroll
        for (int r = 0; r < 8; r++) {
            int e = r*256 + tid; int oo = e >> 5, cc = e & 31;
            int o = o0 + oo;
            const float* Wr = (o < 32) ? (Wq + o*CC)
                            : (o < 64) ? (Wk + (o-32)*CC)
                                       : (Wv + (o-64)*CC);
            ws[oo*40 + cc] = tf32r(Wr[c0 + cc]);
        }
        __syncthreads();
#pragma unroll
        for (int k4 = 0; k4 < 4; k4++) {
            int k0 = k4*8;
            unsigned a0 = FU(xs[(k0 + tig)*XS     + sw*16 + g]);
            unsigned a1 = FU(xs[(k0 + tig)*XS     + sw*16 + 8 + g]);
            unsigned a2 = FU(xs[(k0 + tig + 4)*XS + sw*16 + g]);
            unsigned a3 = FU(xs[(k0 + tig + 4)*XS + sw*16 + 8 + g]);
#pragma unroll
            for (int t8 = 0; t8 < 4; t8++) {
                int oc = np*32 + t8*8 + g;
                unsigned b0 = FU(ws[oc*40 + k0 + tig]);
                unsigned b1 = FU(ws[oc*40 + k0 + tig + 4]);
                mma8(acc[t8], a0, a1, a2, a3, b0, b1);
            }
        }
    }
#pragma unroll
    for (int t8 = 0; t8 < 4; t8++) {
#pragma unroll
        for (int rr = 0; rr < 2; rr++) {
            int n = n0 + sw*16 + g + rr*8;
            int o = o0 + np*32 + t8*8 + 2*tig;
            float v0 = acc[t8][rr*2 + 0];
            float v1 = acc[t8][rr*2 + 1];
            if (o < 32) {
                *(__half2*)(g_qh + (b*NN + n)*QKD + o) =
                    __floats2half2_rn((v0 + __ldg(bq + o)) * SCALE,
                                      (v1 + __ldg(bq + o + 1)) * SCALE);
            } else if (o < 64) {
                *(__half2*)(g_kh + (b*NN + n)*QKD + (o - 32)) =
                    __floats2half2_rn(v0 + __ldg(bk + o - 32),
                                      v1 + __ldg(bk + o - 31));
            } else {
                *(__half2*)(g_vth + (size_t)(b*NN + n)*CC + (o - 64)) =
                    __floats2half2_rn(v0 + __ldg(bv + o - 64),
                                      v1 + __ldg(bv + o - 63));
            }
        }
    }
}

// ---------------- norms: kn2 + block-max qn2 -> atomicMax qmax ---------------
__global__ void bound_norms() {
    __shared__ float s[256];
    int idx = blockIdx.x*256 + threadIdx.x;
    int b = idx >> 12;
    const __half* qp = g_qh + idx*QKD;
    const __half* kp = g_kh + idx*QKD;
    float qs = 0.f, ks = 0.f;
#pragma unroll
    for (int j = 0; j < QKD/2; j++) {
        float2 q2 = __half22float2(*(const __half2*)(qp + 2*j));
        float2 k2 = __half22float2(*(const __half2*)(kp + 2*j));
        qs = fmaf(q2.x, q2.x, qs); qs = fmaf(q2.y, q2.y, qs);
        ks = fmaf(k2.x, k2.x, ks); ks = fmaf(k2.y, k2.y, ks);
    }
    g_kn2[idx] = ks;
    s[threadIdx.x] = qs; __syncthreads();
    for (int st = 128; st > 0; st >>= 1) {
        if (threadIdx.x < st) s[threadIdx.x] = fmaxf(s[threadIdx.x], s[threadIdx.x + st]);
        __syncthreads();
    }
    if (threadIdx.x == 0)
        atomicMax((int*)&g_qmax[b], __float_as_int(s[0]));
}

// ---------------- stats5: pipelined logits(mma) -> exp2 -> S[n], E fp16 ------
// smem: Mch 512B | ks 10240B | qs0 5120B | qs1 5120B | Eh 17408B = 38400B
// Mch holds M' * log2(e); exponent computed as ex2(d*L2E - Mch).
__global__ void stats5() {
    extern __shared__ char smc[];
    float*  Mch = (float*)smc;
    __half* ks  = (__half*)(smc + 512);
    __half* Eh  = (__half*)(smc + 20992);
    unsigned sb = s2u(smc);

    int b = blockIdx.y, n0 = blockIdx.x*128;
    int tid = threadIdx.x, w = tid >> 5, lane = tid & 31, g = lane >> 2, tig = lane & 3;

    // k tile: 128 rows x 32 halves = 512 uint4 (4 per row)
#pragma unroll
    for (int r = 0; r < 2; r++) {
        int e = r*256 + tid; int row = e >> 2, part = e & 3;
        *(uint4*)(ks + row*40 + part*8) =
            *(const uint4*)(g_kh + (b*NN + n0 + row)*QKD + part*8);
    }
    if (tid < 128)
        Mch[tid] = sqrtf(g_kn2[b*NN + n0 + tid] * g_qmax[b]) * L2E;
    __syncthreads();

    unsigned bb[2][2][2];
#pragma unroll
    for (int t = 0; t < 2; t++) {
        int nb = w*16 + t*8;
#pragma unroll
        for (int k2 = 0; k2 < 2; k2++) {
            const __half* p = ks + (nb + g)*40 + k2*16 + 2*tig;
            bb[t][k2][0] = LH2(p);
            bb[t][k2][1] = LH2(p + 8);
        }
    }

    int qrow = tid >> 2, qc8 = (tid & 3)*8;
    const __half* qsrc = g_qh + ((size_t)(b*NN) + qrow)*QKD + qc8;
    unsigned qdst = sb + 10752 + (qrow*40 + qc8)*2;
    unsigned abase = sb + 10752 + ((lane & 15)*40 + ((lane & 16) >> 1))*2;
    CPA(qdst, qsrc); CPCOMMIT();

    float scol[4] = {0.f, 0.f, 0.f, 0.f};
    for (int it = 0; it < 64; it++) {
        if (it + 1 < 64) {
            CPA(qdst + ((it + 1) & 1)*5120, qsrc + (it + 1)*64*QKD);
            CPCOMMIT();
            CPWAIT1();
        } else {
            CPWAIT0();
        }
        __syncthreads();
        unsigned qb = abase + (it & 1)*5120;
#pragma unroll
        for (int sw = 0; sw < 4; sw++) {
            unsigned a[2][4];
            LDSM4(a[0][0], a[0][1], a[0][2], a[0][3], qb + sw*1280);
            LDSM4(a[1][0], a[1][1], a[1][2], a[1][3], qb + sw*1280 + 32);
#pragma unroll
            for (int t = 0; t < 2; t++) {
                float d[4] = {0.f, 0.f, 0.f, 0.f};
#pragma unroll
                for (int k2 = 0; k2 < 2; k2++)
                    mma16(d, a[k2][0], a[k2][1], a[k2][2], a[k2][3],
                          bb[t][k2][0], bb[t][k2][1]);
                int nb = w*16 + t*8;
                float M0 = Mch[nb + 2*tig], M1 = Mch[nb + 2*tig + 1];
                float e0 = fex2(fmaf(d[0], L2E, -M0));
                float e1 = fex2(fmaf(d[1], L2E, -M1));
                float e2 = fex2(fmaf(d[2], L2E, -M0));
                float e3 = fex2(fmaf(d[3], L2E, -M1));
                scol[t*2]     += e0 + e2;
                scol[t*2 + 1] += e1 + e3;
                int col = nb + 2*tig;
                *(__half2*)(Eh + (sw*16 + g)*EHS     + col) = __floats2half2_rn(e0, e1);
                *(__half2*)(Eh + (sw*16 + 8 + g)*EHS + col) = __floats2half2_rn(e2, e3);
            }
        }
        __syncthreads();
#pragma unroll
        for (int r = 0; r < 4; r++) {
            int e = r*256 + tid;
            int row = e >> 4, q4 = e & 15;
            uint4 val = *(const uint4*)(Eh + row*EHS + q4*8);
            *(uint4*)(g_E + ((size_t)(b*NN + it*64 + row))*NN + n0 + q4*8) = val;
        }
    }
#pragma unroll
    for (int off = 16; off >= 4; off >>= 1)
#pragma unroll
        for (int i = 0; i < 4; i++)
            scol[i] += __shfl_down_sync(0xffffffffu, scol[i], off);
    if (lane < 4) {
#pragma unroll
        for (int t = 0; t < 2; t++)
#pragma unroll
            for (int p = 0; p < 2; p++) {
                int n = w*16 + t*8 + 2*lane + p;
                g_invS[b*NN + n0 + n] = 1.f / scol[t*2 + p];
            }
    }
}

// ---------------- vprep: g_vh[b][c][n] = half(v[n][c] * invS[n]) -------------
__global__ void vprep() {
    __shared__ float s[32][33];
    int b = blockIdx.z, c0 = blockIdx.y*32, n0 = blockIdx.x*32;
    int tx = threadIdx.x, ty = threadIdx.y;
#pragma unroll
    for (int r = 0; r < 4; r++) {
        int n = n0 + ty + 8*r;
        s[ty + 8*r][tx] = __half2float(g_vth[(size_t)(b*NN + n)*CC + c0 + tx])
                          * g_invS[b*NN + n];
    }
    __syncthreads();
#pragma unroll
    for (int r = 0; r < 4; r++) {
        int c = c0 + ty + 8*r;
        g_vh[((size_t)b*CC + c)*NN + n0 + tx] = __float2half(s[tx][ty + 8*r]);
    }
}

// ---------------- attnout6: n-tile 64, cp.async 2-stage + ldmatrix -----------
// stage layout (halves, stride 72): Es 128x72 @0, Vs 256x72 @9216 -> 27648 halves
#define ASTG_H 27648
#define ASTG_B 55296
__global__ void __launch_bounds__(512) attnout6() {
    extern __shared__ __half smh[];
    unsigned sb = s2u(smh);

    int b = blockIdx.y, m0 = blockIdx.x*128;
    int tid = threadIdx.x, lane = tid & 31, w = tid >> 5, g = lane >> 2, tig = lane & 3;
    int mw = w & 3, cw = w >> 2;   // m = mw*32, col = cw*64

    // cp.async mapping: E 1024 uint4 (2/thread), V 2048 uint4 (4/thread)
    int er0 = tid >> 3, ep0 = (tid & 7)*8;
    const __half* eS0 = g_E + ((size_t)(b*NN + m0 + er0))*NN + ep0;
    const __half* eS1 = g_E + ((size_t)(b*NN + m0 + 64 + er0))*NN + ep0;
    unsigned eD0 = sb + (er0*72 + ep0)*2;
    unsigned eD1 = sb + ((64 + er0)*72 + ep0)*2;
    const __half* vS[4]; unsigned vD[4];
#pragma unroll
    for (int j = 0; j < 4; j++) {
        int vr = j*64 + er0;
        vS[j] = g_vh + ((size_t)(b*CC + vr))*NN + ep0;
        vD[j] = sb + (9216 + vr*72 + ep0)*2;
    }

    // ldmatrix base offsets (bytes, within stage)
    unsigned ab = ((mw*32 + (lane & 15))*72 + ((lane & 16) >> 1)) * 2;
    unsigned bbase = (9216 + (cw*64 + ((lane & 16) >> 1) + (lane & 7))*72
                      + ((lane & 8) ? 8 : 0)) * 2;

    float acc[2][8][4];
#pragma unroll
    for (int ms = 0; ms < 2; ms++)
#pragma unroll
        for (int i = 0; i < 8; i++)
#pragma unroll
            for (int j = 0; j < 4; j++) acc[ms][i][j] = 0.f;

    // prologue: stage 0 (n = 0)
    CPA(eD0, eS0); CPA(eD1, eS1);
#pragma unroll
    for (int j = 0; j < 4; j++) CPA(vD[j], vS[j]);
    CPCOMMIT();

    for (int it = 0; it < 64; it++) {
        if (it + 1 < 64) {
            int n1 = (it + 1)*64;
            unsigned so = ((it + 1) & 1)*ASTG_B;
            CPA(eD0 + so, eS0 + n1); CPA(eD1 + so, eS1 + n1);
#pragma unroll
            for (int j = 0; j < 4; j++) CPA(vD[j] + so, vS[j] + n1);
            CPCOMMIT();
            CPWAIT1();
        } else {
            CPWAIT0();
        }
        __syncthreads();
        unsigned sbase = sb + (it & 1)*ASTG_B;
#pragma unroll
        for (int k2 = 0; k2 < 4; k2++) {
            unsigned a0[4], a1[4];
            LDSM4(a0[0], a0[1], a0[2], a0[3], sbase + ab + k2*32);
            LDSM4(a1[0], a1[1], a1[2], a1[3], sbase + ab + 2304 + k2*32);
#pragma unroll
            for (int pr = 0; pr < 4; pr++) {
                unsigned b0, b1, c0, c1;
                LDSM4(b0, b1, c0, c1, sbase + bbase + pr*2304 + k2*32);
                mma16(acc[0][2*pr],     a0[0], a0[1], a0[2], a0[3], b0, b1);
                mma16(acc[1][2*pr],     a1[0], a1[1], a1[2], a1[3], b0, b1);
                mma16(acc[0][2*pr + 1], a0[0], a0[1], a0[2], a0[3], c0, c1);
                mma16(acc[1][2*pr + 1], a1[0], a1[1], a1[2], a1[3], c0, c1);
            }
        }
        __syncthreads();
    }
#pragma unroll
    for (int ms = 0; ms < 2; ms++) {
        size_t row = (size_t)(b*NN + m0 + mw*32 + ms*16 + g);
#pragma unroll
        for (int t8 = 0; t8 < 8; t8++) {
            int col = cw*64 + t8*8 + 2*tig;
            *(__half2*)(g_xh + row*CC + col) =
                __floats2half2_rn(acc[ms][t8][0], acc[ms][t8][1]);
            *(__half2*)(g_xh + (row + 8)*CC + col) =
                __floats2half2_rn(acc[ms][t8][2], acc[ms][t8][3]);
        }
    }
}

// ---------------- MLP fp16 (ldmatrix) + LN partials, fp16 output -------------
__global__ void __launch_bounds__(256, 2) mlp5(const float* __restrict__ b1,
                                               const float* __restrict__ b2) {
    extern __shared__ __half smh[];
    __half* Xs  = smh;                   // 64*264
    __half* W1s = Xs  + 64*264;          // 32*264
    __half* Hs  = W1s + 32*264;          // 64*40
    __half* W2s = Hs  + 64*40;           // 256*40

    int m0 = blockIdx.x*64;
    int tid = threadIdx.x, w = tid >> 5, lane = tid & 31, g = lane >> 2, tig = lane & 3;
    int sw = w & 3, np = w >> 2;   // GEMM1 roles
    int m2 = w & 1, c4 = w >> 1;   // GEMM2 roles

    unsigned aadr1 = s2u(Xs)  + ((sw*16 + (lane & 15))*264 + ((lane & 16) >> 1))*2;
    unsigned badr1 = s2u(W1s) + ((np*16 + ((lane & 16) >> 1) + (lane & 7))*264
                                 + ((lane & 8) ? 8 : 0))*2;
    unsigned hadr  = s2u(Hs)  + ((m2*32 + (lane & 15))*40 + ((lane & 16) >> 1))*2;
    unsigned w2adr = s2u(W2s) + ((c4*64 + ((lane & 16) >> 1) + (lane & 7))*40
                                 + ((lane & 8) ? 8 : 0))*2;

#pragma unroll
    for (int r = 0; r < 8; r++) {
        int e = r*256 + tid; int row = e >> 5, q = e & 31;
        *(uint4*)(Xs + row*264 + q*8) =
            *(const uint4*)(g_xh + (size_t)(m0 + row)*CC + q*8);
    }

    float acc2[2][8][4];
#pragma unroll
    for (int ms = 0; ms < 2; ms++)
#pragma unroll
        for (int i = 0; i < 8; i++)
#pragma unroll
            for (int j = 0; j < 4; j++) acc2[ms][i][j] = 0.f;

    for (int slab = 0; slab < 8; slab++) {
        __syncthreads();
#pragma unroll
        for (int r = 0; r < 16; r++) {
            int e = r*256 + tid; int row = e >> 7, c2 = e & 127;
            *(__half2*)(W1s + row*264 + 2*c2) =
                *(const __half2*)(g_W1h + (slab*32 + row)*CC + 2*c2);
        }
#pragma unroll
        for (int r = 0; r < 16; r++) {
            int e = r*256 + tid; int row = e >> 4, c2 = e & 15;
            *(__half2*)(W2s + row*40 + 2*c2) =
                *(const __half2*)(g_W2h + row*CC + slab*32 + 2*c2);
        }
        __syncthreads();
        float acc1[2][4];
#pragma unroll
        for (int t = 0; t < 2; t++)
#pragma unroll
            for (int j = 0; j < 4; j++) acc1[t][j] = 0.f;
#pragma unroll
        for (int k2 = 0; k2 < 16; k2++) {
            unsigned a0, a1, a2, a3, b0, b1, c0, c1;
            LDSM4(a0, a1, a2, a3, aadr1 + k2*32);
            LDSM4(b0, b1, c0, c1, badr1 + k2*32);
            mma16(acc1[0], a0, a1, a2, a3, b0, b1);
            mma16(acc1[1], a0, a1, a2, a3, c0, c1);
        }
#pragma unroll
        for (int t = 0; t < 2; t++) {
            int nb = np*16 + t*8;
            float bb0 = b1[slab*32 + nb + 2*tig];
            float bb1 = b1[slab*32 + nb + 2*tig + 1];
            *(__half2*)(Hs + (sw*16 + g)*40 + nb + 2*tig) =
                __floats2half2_rn(fmaxf(acc1[t][0] + bb0, 0.f), fmaxf(acc1[t][1] + bb1, 0.f));
            *(__half2*)(Hs + (sw*16 + 8 + g)*40 + nb + 2*tig) =
                __floats2half2_rn(fmaxf(acc1[t][2] + bb0, 0.f), fmaxf(acc1[t][3] + bb1, 0.f));
        }
        __syncthreads();
#pragma unroll
        for (int k2 = 0; k2 < 2; k2++) {
            unsigned a0[4], a1[4];
            LDSM4(a0[0], a0[1], a0[2], a0[3], hadr + k2*32);
            LDSM4(a1[0], a1[1], a1[2], a1[3], hadr + 1280 + k2*32);
#pragma unroll
            for (int pr = 0; pr < 4; pr++) {
                unsigned b0, b1, c0, c1;
                LDSM4(b0, b1, c0, c1, w2adr + pr*1280 + k2*32);
                mma16(acc2[0][2*pr],     a0[0], a0[1], a0[2], a0[3], b0, b1);
                mma16(acc2[1][2*pr],     a1[0], a1[1], a1[2], a1[3], b0, b1);
                mma16(acc2[0][2*pr + 1], a0[0], a0[1], a0[2], a0[3], c0, c1);
                mma16(acc2[1][2*pr + 1], a1[0], a1[1], a1[2], a1[3], c0, c1);
            }
        }
    }
    // epilogue + b2 + LN block partials (partials from fp32 pre-rounding)
    float bs = 0.f, bqq = 0.f;
#pragma unroll
    for (int ms = 0; ms < 2; ms++) {
        int row = m0 + m2*32 + ms*16 + g;
#pragma unroll
        for (int t8 = 0; t8 < 8; t8++) {
            int col = c4*64 + t8*8 + 2*tig;
            float v0 = acc2[ms][t8][0] + b2[col];
            float v1 = acc2[ms][t8][1] + b2[col + 1];
            float v2 = acc2[ms][t8][2] + b2[col];
            float v3 = acc2[ms][t8][3] + b2[col + 1];
            *(__half2*)(g_mlph + (size_t)row*CC + col)       = __floats2half2_rn(v0, v1);
            *(__half2*)(g_mlph + (size_t)(row + 8)*CC + col) = __floats2half2_rn(v2, v3);
            bs  += v0 + v1 + v2 + v3;
            bqq += v0*v0 + v1*v1 + v2*v2 + v3*v3;
        }
    }
    __syncthreads();
    float* red = (float*)smh;
    red[tid] = bs; red[256 + tid] = bqq;
    __syncthreads();
    for (int st = 128; st > 0; st >>= 1) {
        if (tid < st) { red[tid] += red[tid + st]; red[256 + tid] += red[256 + tid + st]; }
        __syncthreads();
    }
    if (tid == 0) {
        g_red[blockIdx.x*2 + 0] = red[0];
        g_red[blockIdx.x*2 + 1] = red[256];
    }
}

// ---------------- LayerNorm --------------------------------------------------
__global__ void ln_final() {
    __shared__ float ss[64], sq[64];
    int b = blockIdx.x, t = threadIdx.x;
    ss[t] = g_red[(b*64 + t)*2 + 0];
    sq[t] = g_red[(b*64 + t)*2 + 1];
    __syncthreads();
    for (int st = 32; st > 0; st >>= 1) {
        if (t < st) { ss[t] += ss[t + st]; sq[t] += sq[t + st]; }
        __syncthreads();
    }
    if (t == 0) {
        const float inv = 1.0f / (float)(NN * CC);
        float mean = ss[0] * inv;
        float var  = sq[0] * inv - mean*mean;
        g_mv[b*2 + 0] = mean;
        g_mv[b*2 + 1] = rsqrtf(var + 1e-5f);
    }
}

__global__ void ln_apply(const float* __restrict__ gamma,
                         const float* __restrict__ beta,
                         float* __restrict__ out) {
    __shared__ float s[32][33];
    int b = blockIdx.z, c0 = blockIdx.y*32, n0 = blockIdx.x*32;
    int tx = threadIdx.x, ty = threadIdx.y;
    float mean = g_mv[b*2], rstd = g_mv[b*2 + 1];
#pragma unroll
    for (int r = 0; r < 4; r++) {
        int n = n0 + ty + 8*r;
        s[ty + 8*r][tx] = __half2float(g_mlph[(size_t)(b*NN + n)*CC + c0 + tx]);
    }
    __syncthreads();
#pragma unroll
    for (int r = 0; r < 4; r++) {
        int c = c0 + ty + 8*r;
        int n = n0 + tx;
        float v = s[tx][ty + 8*r];
        size_t gi = (size_t)c*NN + n;
        out[(size_t)b*CC*NN + gi] = (v - mean)*rstd*gamma[gi] + beta[gi];
    }
}

// ---------------- launch ----------------------------------------------------
extern "C" void kernel_launch(void* const* d_in, const int* in_sizes, int n_in,
                              void* d_out, int out_size) {
    const float* x     = (const float*)d_in[0];
    const float* Wq    = (const float*)d_in[1];
    const float* bq    = (const float*)d_in[2];
    const float* Wk    = (const float*)d_in[3];
    const float* bk    = (const float*)d_in[4];
    const float* Wv    = (const float*)d_in[5];
    const float* bv    = (const float*)d_in[6];
    const float* W1    = (const float*)d_in[7];
    const float* b1    = (const float*)d_in[8];
    const float* W2    = (const float*)d_in[9];
    const float* b2    = (const float*)d_in[10];
    const float* gamma = (const float*)d_in[11];
    const float* beta  = (const float*)d_in[12];
    float* out = (float*)d_out;

    const int stats_smem = 38400;
    const int attn_smem  = 2*ASTG_B;                              // 110592
    const int mlp_smem   = (64*264 + 32*264 + 64*40 + 256*40)*2;  // 76288
    cudaFuncSetAttribute(stats5,   cudaFuncAttributeMaxDynamicSharedMemorySize, stats_smem);
    cudaFuncSetAttribute(attnout6, cudaFuncAttributeMaxDynamicSharedMemorySize, attn_smem);
    cudaFuncSetAttribute(mlp5,     cudaFuncAttributeMaxDynamicSharedMemorySize, mlp_smem);

    wprep<<<(2*CC*CC)/256, 256>>>(W1, W2);
    qkv_mma<<<dim3(NN/64, 5, BB), 256>>>(x, Wq, bq, Wk, bk, Wv, bv);
    bound_norms<<<(BB*NN)/256, 256>>>();
    stats5<<<dim3(NN/128, BB), 256, stats_smem>>>();
    vprep<<<dim3(NN/32, CC/32, BB), dim3(32, 8)>>>();
    attnout6<<<dim3(NN/128, BB), 512, attn_smem>>>();
    mlp5<<<(BB*NN)/64, 256, mlp_smem>>>(b1, b2);
    ln_final<<<BB, 64>>>();
    ln_apply<<<dim3(NN/32, CC/32, BB), dim3(32, 8)>>>(gamma, beta, out);
}